// round 10
// baseline (speedup 1.0000x reference)
#include <cuda_runtime.h>
#include <cuda_fp16.h>
#include <cuda_fp8.h>
#include <math.h>

// StateNeuronSep: Luenberger observer, ORDER=4096, SEQ=4096, IN=8, OUT=1.
//
// y_t = r_t.h0 + sum_{k<t} [ (r_k B').u_{t-1-k} + (r_k L) yobs_{t-1-k} ] + D.u_t
// r_{k+1} = r_k A - (r_k.L) C   (row Krylov, rank-1 fold; M never materialized)
// Precision ladder on A:  k in [0,8) fp32 | [8,48) fp16 | [48,128) fp8 e4m3 x2^14.
// ALL steps run inside ONE persistent kernel (128 co-resident CTAs) with a
// software grid barrier between steps — removes ~127 kernel-launch boundaries.

#define Nn 4096
#define Tt 4096
#define INW 8
#define K_TR 128
#define K_F32 8
#define FP8_START 48
#define QP 4
#define NCTA 128
#define FP8_SCALE_INV 6.103515625e-05f   // 2^-14

// Scratch (device globals; no allocation allowed)
__device__ float   g_R[K_TR][QP][Nn];            // partial planes (phi reads all k)
__device__ float   g_S[K_TR][NCTA];              // per-CTA partial s = r.L
__device__ float   g_PQ[K_TR][12];               // p[0..7], [8]=s_k, [9]=r_k.1
__device__ __half2 g_Ah[(Nn * Nn) / 2];          // 32 MB fp16 A
__device__ unsigned long long g_A8[(Nn * Nn) / 8];  // 16 MB fp8 (e4m3, x2^14) A
__device__ unsigned int g_bar = 0;               // grid barrier arrive counter
__device__ unsigned int g_gen = 0;               // grid barrier generation

// ---------------------------------------------------------------------------
// one-time A (fp32) -> fp16 + scaled fp8.  4M float4 elements.
__global__ void __launch_bounds__(256) convert_kernel(const float4* __restrict__ A4) {
    int idx = blockIdx.x * 256 + threadIdx.x;      // 0 .. 4M-1
    float4 v = A4[idx];
    __half2 h0 = __floats2half2_rn(v.x, v.y);
    __half2 h1 = __floats2half2_rn(v.z, v.w);
    uint2 packed;
    packed.x = *reinterpret_cast<unsigned int*>(&h0);
    packed.y = *reinterpret_cast<unsigned int*>(&h1);
    ((uint2*)g_Ah)[idx] = packed;
    const float sc = 16384.f;                      // max |A|*2^14 ~ 399 < 448
    unsigned int b0 = __nv_cvt_float_to_fp8(v.x * sc, __NV_SATFINITE, __NV_E4M3);
    unsigned int b1 = __nv_cvt_float_to_fp8(v.y * sc, __NV_SATFINITE, __NV_E4M3);
    unsigned int b2 = __nv_cvt_float_to_fp8(v.z * sc, __NV_SATFINITE, __NV_E4M3);
    unsigned int b3 = __nv_cvt_float_to_fp8(v.w * sc, __NV_SATFINITE, __NV_E4M3);
    ((unsigned int*)g_A8)[idx] = b0 | (b1 << 8) | (b2 << 16) | (b3 << 24);
}

// ---------------------------------------------------------------------------
// init: r_0 = C in plane 0, zeros elsewhere; block 0 computes s_0 = C.L.
__global__ void init_kernel(const float* __restrict__ C,
                            const float* __restrict__ L) {
    __shared__ float red[256];
    int tid = threadIdx.x;
    int j = blockIdx.x * 256 + tid;
    if (j < Nn) {
        g_R[0][0][j] = C[j];
        g_R[0][1][j] = 0.f;
        g_R[0][2][j] = 0.f;
        g_R[0][3][j] = 0.f;
    }
    if (blockIdx.x == 0) {
        float sp = 0.f;
        for (int i = tid; i < Nn; i += 256) sp += C[i] * L[i];
        red[tid] = sp;
        __syncthreads();
        for (int off = 128; off > 0; off >>= 1) {
            if (tid < off) red[tid] += red[tid + off];
            __syncthreads();
        }
        if (tid == 0) g_S[0][0] = red[0];
    }
}

// ---------------------------------------------------------------------------
// Sense-reversing software grid barrier (all NCTA CTAs co-resident).
// release: threadfence + relaxed arrive; last CTA resets counter and bumps
// generation with red.release; waiters acquire-spin on the generation.
__device__ __forceinline__ void grid_sync() {
    __syncthreads();
    if (threadIdx.x == 0) {
        unsigned int gen;
        asm volatile("ld.acquire.gpu.global.u32 %0, [%1];"
                     : "=r"(gen) : "l"(&g_gen));
        __threadfence();
        unsigned int old = atomicAdd(&g_bar, 1u);
        if (old == NCTA - 1u) {
            g_bar = 0u;
            asm volatile("red.release.gpu.global.add.u32 [%0], 1;"
                         :: "l"(&g_gen));
        } else {
            unsigned int cur;
            do {
                asm volatile("ld.acquire.gpu.global.u32 %0, [%1];"
                             : "=r"(cur) : "l"(&g_gen));
            } while (cur == gen);
        }
    }
    __syncthreads();
}

// ---------------------------------------------------------------------------
// Persistent step chain: 128 CTAs x 512 threads run all K_TR-1 Krylov steps.
// CTA b: quarter = b>>5 (row quarter), coltile = b&31 (128-col tile).
__global__ void __launch_bounds__(512) steps_kernel(const float* __restrict__ A,
                                                    const float* __restrict__ C,
                                                    const float* __restrict__ L) {
    __shared__ __align__(16) float r_s[1024];   // own row-quarter slice of r_k
    __shared__ float acc_s[16][128];
    __shared__ float dot_s[128];
    __shared__ float s_sh;

    int tid  = threadIdx.x;
    int lane = tid & 31;
    int w    = tid >> 5;
    int b    = blockIdx.x;
    int quarter = b >> 5;                 // 0..3
    int coltile = b & 31;                 // 0..31
    int colbase = coltile * 128;
    int rowg    = quarter * 1024 + w * 64;   // global base row for this warp
    int il      = w * 64;                    // local base row in r_s

    const unsigned long long* A32u = (const unsigned long long*)A;     // float2
    const unsigned long long* A16u = (const unsigned long long*)g_Ah;  // 4 halves
    const unsigned long long* A8u  = g_A8;                             // 8 e4m3

    for (int k = 0; k < K_TR - 1; k++) {
        int cnt = (k == 0) ? 1 : NCTA;

        // ---- prologue: slice-assemble r_k; one warp sums the s partials ----
        if (tid < 256) {
            const float4* p0 = (const float4*)&g_R[k][0][quarter * 1024];
            const float4* p1 = (const float4*)&g_R[k][1][quarter * 1024];
            const float4* p2 = (const float4*)&g_R[k][2][quarter * 1024];
            const float4* p3 = (const float4*)&g_R[k][3][quarter * 1024];
            float4 a = p0[tid], bb = p1[tid], c = p2[tid], d = p3[tid];
            ((float4*)r_s)[tid] =
                make_float4(a.x + bb.x + c.x + d.x, a.y + bb.y + c.y + d.y,
                            a.z + bb.z + c.z + d.z, a.w + bb.w + c.w + d.w);
        } else if (tid >= 480) {
            int l2 = tid - 480;
            float sp = 0.f;
            for (int idx = l2; idx < cnt; idx += 32) sp += g_S[k][idx];
            #pragma unroll
            for (int off = 16; off > 0; off >>= 1)
                sp += __shfl_xor_sync(0xffffffffu, sp, off);
            if (l2 == 0) s_sh = sp;
        }
        __syncthreads();

        float scale = 1.f;

        // ---- mainloop: precision ladder ----
        if (k < K_F32) {
            // fp32: two 64-col half-passes, float2 loads + packed FFMA2
            #pragma unroll
            for (int hp = 0; hp < 2; hp++) {
                size_t c2 = (size_t)((colbase + hp * 64) >> 1) + lane;
                unsigned long long acc0 = 0ull, acc1 = 0ull;
                #pragma unroll 4
                for (int ii = 0; ii < 64; ii += 2) {
                    float r0 = r_s[il + ii];
                    float r1 = r_s[il + ii + 1];
                    size_t gi = (size_t)(rowg + ii);
                    unsigned long long a0 = A32u[gi * (Nn / 2) + c2];
                    unsigned long long a1 = A32u[(gi + 1) * (Nn / 2) + c2];
                    unsigned long long rr0, rr1;
                    asm("mov.b64 %0, {%1, %1};" : "=l"(rr0) : "r"(__float_as_uint(r0)));
                    asm("mov.b64 %0, {%1, %1};" : "=l"(rr1) : "r"(__float_as_uint(r1)));
                    asm("fma.rn.f32x2 %0, %1, %2, %3;" : "=l"(acc0) : "l"(a0), "l"(rr0), "l"(acc0));
                    asm("fma.rn.f32x2 %0, %1, %2, %3;" : "=l"(acc1) : "l"(a1), "l"(rr1), "l"(acc1));
                }
                unsigned long long accm;
                asm("add.rn.f32x2 %0, %1, %2;" : "=l"(accm) : "l"(acc0), "l"(acc1));
                unsigned int lo_u, hi_u;
                asm("mov.b64 {%0, %1}, %2;" : "=r"(lo_u), "=r"(hi_u) : "l"(accm));
                acc_s[w][hp * 64 + lane * 2]     = __uint_as_float(lo_u);
                acc_s[w][hp * 64 + lane * 2 + 1] = __uint_as_float(hi_u);
            }
        } else if (k < FP8_START) {
            // fp16: lane covers 4 consecutive cols (u64 = 4 halves)
            size_t c4 = (size_t)(colbase >> 2) + lane;
            float a0 = 0.f, a1 = 0.f, a2 = 0.f, a3 = 0.f;
            #pragma unroll 4
            for (int ii = 0; ii < 64; ii++) {
                float rv = r_s[il + ii];
                unsigned long long av = A16u[(size_t)(rowg + ii) * (Nn / 4) + c4];
                unsigned int lo = (unsigned int)av;
                unsigned int hi = (unsigned int)(av >> 32);
                float2 f0 = __half22float2(*(__half2*)&lo);
                float2 f1 = __half22float2(*(__half2*)&hi);
                a0 += rv * f0.x; a1 += rv * f0.y;
                a2 += rv * f1.x; a3 += rv * f1.y;
            }
            acc_s[w][lane * 4]     = a0;
            acc_s[w][lane * 4 + 1] = a1;
            acc_s[w][lane * 4 + 2] = a2;
            acc_s[w][lane * 4 + 3] = a3;
        } else {
            // fp8: lane covers 8 cols (u64 = 8 e4m3); half-warps on row parity
            scale = FP8_SCALE_INV;
            int half = lane >> 4;
            int lpos = lane & 15;
            size_t cu = (size_t)(colbase >> 3) + lpos;
            float acc[8];
            #pragma unroll
            for (int c = 0; c < 8; c++) acc[c] = 0.f;
            #pragma unroll 4
            for (int ii = 0; ii < 64; ii += 2) {
                float rv = r_s[il + ii + half];
                unsigned long long av = A8u[(size_t)(rowg + ii + half) * (Nn / 8) + cu];
                unsigned short p0 = (unsigned short)av;
                unsigned short p1 = (unsigned short)(av >> 16);
                unsigned short p2 = (unsigned short)(av >> 32);
                unsigned short p3 = (unsigned short)(av >> 48);
                unsigned int h01, h23, h45, h67;
                asm("cvt.rn.f16x2.e4m3x2 %0, %1;" : "=r"(h01) : "h"(p0));
                asm("cvt.rn.f16x2.e4m3x2 %0, %1;" : "=r"(h23) : "h"(p1));
                asm("cvt.rn.f16x2.e4m3x2 %0, %1;" : "=r"(h45) : "h"(p2));
                asm("cvt.rn.f16x2.e4m3x2 %0, %1;" : "=r"(h67) : "h"(p3));
                float2 f0 = __half22float2(*(__half2*)&h01);
                float2 f1 = __half22float2(*(__half2*)&h23);
                float2 f2 = __half22float2(*(__half2*)&h45);
                float2 f3 = __half22float2(*(__half2*)&h67);
                acc[0] += rv * f0.x; acc[1] += rv * f0.y;
                acc[2] += rv * f1.x; acc[3] += rv * f1.y;
                acc[4] += rv * f2.x; acc[5] += rv * f2.y;
                acc[6] += rv * f3.x; acc[7] += rv * f3.y;
            }
            #pragma unroll
            for (int c = 0; c < 8; c++)
                acc[c] += __shfl_down_sync(0xffffffffu, acc[c], 16);
            if (lane < 16) {
                #pragma unroll
                for (int c = 0; c < 8; c++)
                    acc_s[w][lpos * 8 + c] = acc[c];
            }
        }
        __syncthreads();

        // ---- epilogue: column reduce, fold -s*C on quarter 0, write plane,
        //      emit per-CTA partial dot with L ----
        if (tid < 128) {
            float t = 0.f;
            #pragma unroll
            for (int q = 0; q < 16; q++) t += acc_s[q][tid];
            t *= scale;
            int j = colbase + tid;
            if (quarter == 0) t -= s_sh * C[j];
            g_R[k + 1][quarter][j] = t;
            dot_s[tid] = t * L[j];
        }
        __syncthreads();
        for (int off = 64; off > 0; off >>= 1) {
            if (tid < off) dot_s[tid] += dot_s[tid + off];
            __syncthreads();
        }
        if (tid == 0) g_S[k + 1][b] = dot_s[0];

        grid_sync();
    }
}

// ---------------------------------------------------------------------------
// phi: p_k = r_k B - s_k D, q_k = s_k = r_k.L, a_k = r_k.1
__global__ void __launch_bounds__(256) phi_kernel(const float* __restrict__ B,
                                                  const float* __restrict__ D,
                                                  const float* __restrict__ L) {
    __shared__ float r_s[Nn];
    __shared__ float red[256];
    __shared__ float sres[10];
    int k = blockIdx.x;
    int tid = threadIdx.x;

    for (int i = tid; i < Nn; i += 256)
        r_s[i] = g_R[k][0][i] + g_R[k][1][i] + g_R[k][2][i] + g_R[k][3][i];
    __syncthreads();

    float acc[10];
    #pragma unroll
    for (int c = 0; c < 10; c++) acc[c] = 0.f;

    for (int i = tid; i < Nn; i += 256) {
        float rv = r_s[i];
        float4 b0 = *(const float4*)(B + i * INW);
        float4 b1 = *(const float4*)(B + i * INW + 4);
        acc[0] += rv * b0.x; acc[1] += rv * b0.y;
        acc[2] += rv * b0.z; acc[3] += rv * b0.w;
        acc[4] += rv * b1.x; acc[5] += rv * b1.y;
        acc[6] += rv * b1.z; acc[7] += rv * b1.w;
        acc[8] += rv * L[i];
        acc[9] += rv;                 // h0 = ones
    }

    #pragma unroll
    for (int c = 0; c < 10; c++) {
        red[tid] = acc[c];
        __syncthreads();
        for (int off = 128; off > 0; off >>= 1) {
            if (tid < off) red[tid] += red[tid + off];
            __syncthreads();
        }
        if (tid == 0) sres[c] = red[0];
        __syncthreads();
    }

    if (tid == 0) {
        float s = sres[8];
        #pragma unroll
        for (int c = 0; c < INW; c++) g_PQ[k][c] = sres[c] - s * D[c];
        g_PQ[k][8] = s;
        g_PQ[k][9] = sres[9];
    }
}

// ---------------------------------------------------------------------------
// conv: y_t = a_t + D.u_t + sum_{k<min(t,K)} [ p_k.u_{t-1-k} + q_k yobs_{t-1-k} ]
__global__ void __launch_bounds__(256) conv_kernel(const float* __restrict__ u,
                                                   const float* __restrict__ yobs,
                                                   const float* __restrict__ D,
                                                   float* __restrict__ out) {
    __shared__ float pq[K_TR][10];
    __shared__ float us[512][9];      // [local sidx][0..7]=u, [8]=yobs
    int tid = threadIdx.x;
    int t0  = blockIdx.x * 256;

    for (int idx = tid; idx < K_TR * 10; idx += 256)
        pq[idx / 10][idx % 10] = g_PQ[idx / 10][idx % 10];

    for (int l = tid; l < 512; l += 256) {
        int sidx = t0 - 256 + l;
        if (sidx >= 0 && sidx < Tt) {
            #pragma unroll
            for (int c = 0; c < INW; c++) us[l][c] = u[c * Tt + sidx];
            us[l][8] = yobs[sidx];
        } else {
            #pragma unroll
            for (int c = 0; c < 9; c++) us[l][c] = 0.f;
        }
    }
    __syncthreads();

    int t = t0 + tid;
    float y = 0.f;
    #pragma unroll
    for (int c = 0; c < INW; c++) y += D[c] * u[c * Tt + t];
    if (t < K_TR) y += pq[t][9];      // a_t = r_t . h0 (decayed ~0 beyond K)

    int kmax = min(t, K_TR);
    for (int kk = 0; kk < kmax; kk++) {
        int l = tid + 255 - kk;       // (t-1-kk) - (t0-256)
        float a = pq[kk][8] * us[l][8];
        #pragma unroll
        for (int c = 0; c < INW; c++) a += pq[kk][c] * us[l][c];
        y += a;
    }
    out[t] = 3.f * tanhf(y);
}

// ---------------------------------------------------------------------------
extern "C" void kernel_launch(void* const* d_in, const int* in_sizes, int n_in,
                              void* d_out, int out_size) {
    const float* u    = (const float*)d_in[0];  // [8,4096]
    const float* yobs = (const float*)d_in[1];  // [1,4096]
    const float* A    = (const float*)d_in[2];  // [4096,4096]
    const float* B    = (const float*)d_in[3];  // [4096,8]
    const float* C    = (const float*)d_in[4];  // [1,4096]
    const float* D    = (const float*)d_in[5];  // [1,8]
    const float* L    = (const float*)d_in[6];  // [4096,1]
    float* out = (float*)d_out;                 // [1,4096]
    (void)in_sizes; (void)n_in; (void)out_size;

    convert_kernel<<<(Nn * Nn / 4) / 256, 256>>>((const float4*)A);
    init_kernel<<<Nn / 256, 256>>>(C, L);
    steps_kernel<<<NCTA, 512>>>(A, C, L);
    phi_kernel<<<K_TR, 256>>>(B, D, L);
    conv_kernel<<<Tt / 256, 256>>>(u, yobs, D, out);
}

// round 11
// speedup vs baseline: 1.1070x; 1.1070x over previous
#include <cuda_runtime.h>
#include <cuda_fp16.h>
#include <cuda_fp8.h>
#include <math.h>

// StateNeuronSep: Luenberger observer, ORDER=4096, SEQ=4096, IN=8, OUT=1.
//
// y_t = r_t.h0 + sum_{k<t} [ (r_k B').u_{t-1-k} + (r_k L) yobs_{t-1-k} ] + D.u_t
// r_{k+1} = r_k A - (r_k.L) C   (row Krylov, rank-1 fold; M never materialized)
// Ladder: k in [0,8) fp32 (8 multi-launch steps, 256 CTAs) |
//         k in [8,48) fp16, [48,112) fp8 e4m3 x2^14 — ONE persistent kernel,
//         128 CTAs, software grid barrier, cross-barrier A-prefetch into smem.

#define Nn 4096
#define Tt 4096
#define INW 8
#define K_TR 112
#define K_F32 8
#define FP8_START 48
#define QP 4
#define NCTA 128
#define FP8_SCALE_INV 6.103515625e-05f   // 2^-14

// Scratch (device globals; no allocation allowed)
__device__ float   g_R[K_TR][QP][Nn];            // partial planes (phi reads all k)
__device__ float   g_S[K_TR][256];               // per-CTA partial s = r.L
__device__ float   g_PQ[K_TR][12];               // p[0..7], [8]=s_k, [9]=r_k.1
__device__ __half2 g_Ah[(Nn * Nn) / 2];          // 32 MB fp16 A
__device__ unsigned long long g_A8[(Nn * Nn) / 8];  // 16 MB fp8 (e4m3, x2^14) A
__device__ unsigned int g_bar = 0;               // grid barrier arrive counter
__device__ unsigned int g_gen = 0;               // grid barrier generation

// ---------------------------------------------------------------------------
// one-time A (fp32) -> fp16 + scaled fp8.  4M float4 elements.
__global__ void __launch_bounds__(256) convert_kernel(const float4* __restrict__ A4) {
    int idx = blockIdx.x * 256 + threadIdx.x;      // 0 .. 4M-1
    float4 v = A4[idx];
    __half2 h0 = __floats2half2_rn(v.x, v.y);
    __half2 h1 = __floats2half2_rn(v.z, v.w);
    uint2 packed;
    packed.x = *reinterpret_cast<unsigned int*>(&h0);
    packed.y = *reinterpret_cast<unsigned int*>(&h1);
    ((uint2*)g_Ah)[idx] = packed;
    const float sc = 16384.f;                      // max |A|*2^14 ~ 399 < 448
    unsigned int b0 = __nv_cvt_float_to_fp8(v.x * sc, __NV_SATFINITE, __NV_E4M3);
    unsigned int b1 = __nv_cvt_float_to_fp8(v.y * sc, __NV_SATFINITE, __NV_E4M3);
    unsigned int b2 = __nv_cvt_float_to_fp8(v.z * sc, __NV_SATFINITE, __NV_E4M3);
    unsigned int b3 = __nv_cvt_float_to_fp8(v.w * sc, __NV_SATFINITE, __NV_E4M3);
    ((unsigned int*)g_A8)[idx] = b0 | (b1 << 8) | (b2 << 16) | (b3 << 24);
}

// ---------------------------------------------------------------------------
// init: r_0 = C in plane 0, zeros elsewhere; block 0 computes s_0 = C.L;
// also resets the grid-barrier state (required for repeated graph replays).
__global__ void init_kernel(const float* __restrict__ C,
                            const float* __restrict__ L) {
    __shared__ float red[256];
    int tid = threadIdx.x;
    int j = blockIdx.x * 256 + tid;
    if (j < Nn) {
        g_R[0][0][j] = C[j];
        g_R[0][1][j] = 0.f;
        g_R[0][2][j] = 0.f;
        g_R[0][3][j] = 0.f;
    }
    if (blockIdx.x == 1 && tid == 0) { g_bar = 0u; g_gen = 0u; }
    if (blockIdx.x == 0) {
        float sp = 0.f;
        for (int i = tid; i < Nn; i += 256) sp += C[i] * L[i];
        red[tid] = sp;
        __syncthreads();
        for (int off = 128; off > 0; off >>= 1) {
            if (tid < off) red[tid] += red[tid + off];
            __syncthreads();
        }
        if (tid == 0) g_S[0][0] = red[0];
    }
}

// ---------------------------------------------------------------------------
// fp32 step (multi-launch, 256 CTAs — proven R8 shape).
// grid (64 col-tiles of 64, 4 row-quarters), block 512 (16 warps).
__global__ void __launch_bounds__(512) step32_kernel(int k, int cnt,
                                                     const float* __restrict__ A,
                                                     const float* __restrict__ C,
                                                     const float* __restrict__ L) {
    __shared__ __align__(16) float r_s[1024];   // own row-quarter slice
    __shared__ float acc_s[16][64];
    __shared__ float dot_s[64];
    __shared__ float s_sh;

    int tid  = threadIdx.x;
    int lane = tid & 31;
    int w    = tid >> 5;

    // prologue: slice-assemble r_k; one warp sums the s partials
    if (tid < 256) {
        const float4* p0 = (const float4*)&g_R[k][0][blockIdx.y * 1024];
        const float4* p1 = (const float4*)&g_R[k][1][blockIdx.y * 1024];
        const float4* p2 = (const float4*)&g_R[k][2][blockIdx.y * 1024];
        const float4* p3 = (const float4*)&g_R[k][3][blockIdx.y * 1024];
        float4 a = p0[tid], b = p1[tid], c = p2[tid], d = p3[tid];
        ((float4*)r_s)[tid] =
            make_float4(a.x + b.x + c.x + d.x, a.y + b.y + c.y + d.y,
                        a.z + b.z + c.z + d.z, a.w + b.w + c.w + d.w);
    } else if (tid >= 480) {
        int l2 = tid - 480;
        float sp = 0.f;
        for (int idx = l2; idx < cnt; idx += 32) sp += g_S[k][idx];
        #pragma unroll
        for (int off = 16; off > 0; off >>= 1)
            sp += __shfl_xor_sync(0xffffffffu, sp, off);
        if (l2 == 0) s_sh = sp;
    }
    __syncthreads();

    int colbase = blockIdx.x * 64;
    size_t c2   = (size_t)(colbase >> 1) + lane;
    int rowg    = blockIdx.y * 1024 + w * 64;
    int il      = w * 64;

    const unsigned long long* Au = (const unsigned long long*)A;
    unsigned long long acc0 = 0ull, acc1 = 0ull;

    #pragma unroll 4
    for (int ii = 0; ii < 64; ii += 2) {
        float r0 = r_s[il + ii];
        float r1 = r_s[il + ii + 1];
        size_t gi = (size_t)(rowg + ii);
        unsigned long long a0 = Au[gi * (Nn / 2) + c2];
        unsigned long long a1 = Au[(gi + 1) * (Nn / 2) + c2];
        unsigned long long rr0, rr1;
        asm("mov.b64 %0, {%1, %1};" : "=l"(rr0) : "r"(__float_as_uint(r0)));
        asm("mov.b64 %0, {%1, %1};" : "=l"(rr1) : "r"(__float_as_uint(r1)));
        asm("fma.rn.f32x2 %0, %1, %2, %3;" : "=l"(acc0) : "l"(a0), "l"(rr0), "l"(acc0));
        asm("fma.rn.f32x2 %0, %1, %2, %3;" : "=l"(acc1) : "l"(a1), "l"(rr1), "l"(acc1));
    }
    unsigned long long accm;
    asm("add.rn.f32x2 %0, %1, %2;" : "=l"(accm) : "l"(acc0), "l"(acc1));
    unsigned int lo_u, hi_u;
    asm("mov.b64 {%0, %1}, %2;" : "=r"(lo_u), "=r"(hi_u) : "l"(accm));
    acc_s[w][lane * 2]     = __uint_as_float(lo_u);
    acc_s[w][lane * 2 + 1] = __uint_as_float(hi_u);
    __syncthreads();

    if (tid < 64) {
        float t = 0.f;
        #pragma unroll
        for (int q = 0; q < 16; q++) t += acc_s[q][tid];
        int j = colbase + tid;
        if (blockIdx.y == 0) t -= s_sh * C[j];
        g_R[k + 1][blockIdx.y][j] = t;
        dot_s[tid] = t * L[j];
    }
    __syncthreads();
    for (int off = 32; off > 0; off >>= 1) {
        if (tid < off) dot_s[tid] += dot_s[tid + off];
        __syncthreads();
    }
    if (tid == 0)
        g_S[k + 1][blockIdx.y * gridDim.x + blockIdx.x] = dot_s[0];
}

// ---------------------------------------------------------------------------
// Sense-reversing software grid barrier (all NCTA CTAs co-resident).
__device__ __forceinline__ void grid_sync() {
    __syncthreads();
    if (threadIdx.x == 0) {
        unsigned int gen;
        asm volatile("ld.acquire.gpu.global.u32 %0, [%1];"
                     : "=r"(gen) : "l"(&g_gen));
        __threadfence();
        unsigned int old = atomicAdd(&g_bar, 1u);
        if (old == NCTA - 1u) {
            g_bar = 0u;
            asm volatile("red.release.gpu.global.add.u32 [%0], 1;"
                         :: "l"(&g_gen));
        } else {
            unsigned int cur;
            do {
                asm volatile("ld.acquire.gpu.global.u32 %0, [%1];"
                             : "=r"(cur) : "l"(&g_gen));
            } while (cur == gen);
        }
    }
    __syncthreads();
}

// ---------------------------------------------------------------------------
// Persistent fp16/fp8 step chain: 128 CTAs x 512 threads, k in [8, K_TR-1).
// CTA b: quarter = b>>5, coltile = b&31 (128-col tile).
// A-prefetch: before each barrier, issue the next step's first 4 u64 A-loads
// per thread into pref_s (A is constant — race-free), hiding prologue latency.
__global__ void __launch_bounds__(512) steps_pers_kernel(const float* __restrict__ C,
                                                         const float* __restrict__ L) {
    __shared__ __align__(16) float r_s[1024];
    __shared__ float acc_s[16][128];
    __shared__ unsigned long long pref_s[512 * 4];   // 16 KB prefetch buffer
    __shared__ float dotp[4];
    __shared__ float s_sh;

    int tid  = threadIdx.x;
    int lane = tid & 31;
    int w    = tid >> 5;
    int b    = blockIdx.x;
    int quarter = b >> 5;
    int colbase = (b & 31) * 128;
    int rowg    = quarter * 1024 + w * 64;
    int il      = w * 64;

    const unsigned long long* A16u = (const unsigned long long*)g_Ah;  // 4 halves
    const unsigned long long* A8u  = g_A8;                             // 8 e4m3

    int half = lane >> 4;
    int lpos = lane & 15;
    size_t c4 = (size_t)(colbase >> 2) + lane;   // fp16 u64 col index
    size_t cu = (size_t)(colbase >> 3) + lpos;   // fp8  u64 col index

    // prefetch for the first step (k = K_F32, fp16)
    #pragma unroll
    for (int p = 0; p < 4; p++)
        pref_s[tid * 4 + p] = A16u[(size_t)(rowg + p) * (Nn / 4) + c4];

    for (int k = K_F32; k < K_TR - 1; k++) {
        int cnt = (k == K_F32) ? 256 : NCTA;

        // ---- prologue: slice-assemble r_k; one warp sums s partials ----
        if (tid < 256) {
            const float4* p0 = (const float4*)&g_R[k][0][quarter * 1024];
            const float4* p1 = (const float4*)&g_R[k][1][quarter * 1024];
            const float4* p2 = (const float4*)&g_R[k][2][quarter * 1024];
            const float4* p3 = (const float4*)&g_R[k][3][quarter * 1024];
            float4 a = p0[tid], bb = p1[tid], c = p2[tid], d = p3[tid];
            ((float4*)r_s)[tid] =
                make_float4(a.x + bb.x + c.x + d.x, a.y + bb.y + c.y + d.y,
                            a.z + bb.z + c.z + d.z, a.w + bb.w + c.w + d.w);
        } else if (tid >= 480) {
            int l2 = tid - 480;
            float sp = 0.f;
            for (int idx = l2; idx < cnt; idx += 32) sp += g_S[k][idx];
            #pragma unroll
            for (int off = 16; off > 0; off >>= 1)
                sp += __shfl_xor_sync(0xffffffffu, sp, off);
            if (l2 == 0) s_sh = sp;
        }
        __syncthreads();

        float scale = 1.f;

        // ---- mainloop: fp16 or fp8, first loads served from pref_s ----
        if (k < FP8_START) {
            float a0 = 0.f, a1 = 0.f, a2 = 0.f, a3 = 0.f;
            #pragma unroll
            for (int ii = 0; ii < 4; ii++) {             // prefetched rows
                float rv = r_s[il + ii];
                unsigned long long av = pref_s[tid * 4 + ii];
                unsigned int lo = (unsigned int)av;
                unsigned int hi = (unsigned int)(av >> 32);
                float2 f0 = __half22float2(*(__half2*)&lo);
                float2 f1 = __half22float2(*(__half2*)&hi);
                a0 += rv * f0.x; a1 += rv * f0.y;
                a2 += rv * f1.x; a3 += rv * f1.y;
            }
            #pragma unroll 4
            for (int ii = 4; ii < 64; ii++) {
                float rv = r_s[il + ii];
                unsigned long long av = A16u[(size_t)(rowg + ii) * (Nn / 4) + c4];
                unsigned int lo = (unsigned int)av;
                unsigned int hi = (unsigned int)(av >> 32);
                float2 f0 = __half22float2(*(__half2*)&lo);
                float2 f1 = __half22float2(*(__half2*)&hi);
                a0 += rv * f0.x; a1 += rv * f0.y;
                a2 += rv * f1.x; a3 += rv * f1.y;
            }
            acc_s[w][lane * 4]     = a0;
            acc_s[w][lane * 4 + 1] = a1;
            acc_s[w][lane * 4 + 2] = a2;
            acc_s[w][lane * 4 + 3] = a3;
        } else {
            scale = FP8_SCALE_INV;
            float acc[8];
            #pragma unroll
            for (int c = 0; c < 8; c++) acc[c] = 0.f;
            #pragma unroll
            for (int p = 0; p < 4; p++) {                // prefetched rows
                int ii = 2 * p;
                float rv = r_s[il + ii + half];
                unsigned long long av = pref_s[tid * 4 + p];
                unsigned short p0 = (unsigned short)av;
                unsigned short p1 = (unsigned short)(av >> 16);
                unsigned short p2 = (unsigned short)(av >> 32);
                unsigned short p3 = (unsigned short)(av >> 48);
                unsigned int h01, h23, h45, h67;
                asm("cvt.rn.f16x2.e4m3x2 %0, %1;" : "=r"(h01) : "h"(p0));
                asm("cvt.rn.f16x2.e4m3x2 %0, %1;" : "=r"(h23) : "h"(p1));
                asm("cvt.rn.f16x2.e4m3x2 %0, %1;" : "=r"(h45) : "h"(p2));
                asm("cvt.rn.f16x2.e4m3x2 %0, %1;" : "=r"(h67) : "h"(p3));
                float2 f0 = __half22float2(*(__half2*)&h01);
                float2 f1 = __half22float2(*(__half2*)&h23);
                float2 f2 = __half22float2(*(__half2*)&h45);
                float2 f3 = __half22float2(*(__half2*)&h67);
                acc[0] += rv * f0.x; acc[1] += rv * f0.y;
                acc[2] += rv * f1.x; acc[3] += rv * f1.y;
                acc[4] += rv * f2.x; acc[5] += rv * f2.y;
                acc[6] += rv * f3.x; acc[7] += rv * f3.y;
            }
            #pragma unroll 4
            for (int ii = 8; ii < 64; ii += 2) {
                float rv = r_s[il + ii + half];
                unsigned long long av = A8u[(size_t)(rowg + ii + half) * (Nn / 8) + cu];
                unsigned short p0 = (unsigned short)av;
                unsigned short p1 = (unsigned short)(av >> 16);
                unsigned short p2 = (unsigned short)(av >> 32);
                unsigned short p3 = (unsigned short)(av >> 48);
                unsigned int h01, h23, h45, h67;
                asm("cvt.rn.f16x2.e4m3x2 %0, %1;" : "=r"(h01) : "h"(p0));
                asm("cvt.rn.f16x2.e4m3x2 %0, %1;" : "=r"(h23) : "h"(p1));
                asm("cvt.rn.f16x2.e4m3x2 %0, %1;" : "=r"(h45) : "h"(p2));
                asm("cvt.rn.f16x2.e4m3x2 %0, %1;" : "=r"(h67) : "h"(p3));
                float2 f0 = __half22float2(*(__half2*)&h01);
                float2 f1 = __half22float2(*(__half2*)&h23);
                float2 f2 = __half22float2(*(__half2*)&h45);
                float2 f3 = __half22float2(*(__half2*)&h67);
                acc[0] += rv * f0.x; acc[1] += rv * f0.y;
                acc[2] += rv * f1.x; acc[3] += rv * f1.y;
                acc[4] += rv * f2.x; acc[5] += rv * f2.y;
                acc[6] += rv * f3.x; acc[7] += rv * f3.y;
            }
            #pragma unroll
            for (int c = 0; c < 8; c++)
                acc[c] += __shfl_down_sync(0xffffffffu, acc[c], 16);
            if (lane < 16) {
                #pragma unroll
                for (int c = 0; c < 8; c++)
                    acc_s[w][lpos * 8 + c] = acc[c];
            }
        }
        __syncthreads();

        // ---- epilogue: column reduce, fold, write plane, shuffle dot ----
        float d = 0.f;
        if (tid < 128) {
            float t = 0.f;
            #pragma unroll
            for (int q = 0; q < 16; q++) t += acc_s[q][tid];
            t *= scale;
            int j = colbase + tid;
            if (quarter == 0) t -= s_sh * C[j];
            g_R[k + 1][quarter][j] = t;
            d = t * L[j];
            #pragma unroll
            for (int off = 16; off > 0; off >>= 1)
                d += __shfl_xor_sync(0xffffffffu, d, off);
            if (lane == 0) dotp[w] = d;
        }
        __syncthreads();
        if (tid == 0)
            g_S[k + 1][b] = (dotp[0] + dotp[1]) + (dotp[2] + dotp[3]);

        // ---- cross-barrier A-prefetch for step k+1 (A is constant) ----
        int kn = k + 1;
        if (kn < K_TR - 1) {
            if (kn < FP8_START) {
                #pragma unroll
                for (int p = 0; p < 4; p++)
                    pref_s[tid * 4 + p] = A16u[(size_t)(rowg + p) * (Nn / 4) + c4];
            } else {
                #pragma unroll
                for (int p = 0; p < 4; p++)
                    pref_s[tid * 4 + p] = A8u[(size_t)(rowg + 2 * p + half) * (Nn / 8) + cu];
            }
        }

        grid_sync();
    }
}

// ---------------------------------------------------------------------------
// phi: p_k = r_k B - s_k D, q_k = s_k = r_k.L, a_k = r_k.1
__global__ void __launch_bounds__(256) phi_kernel(const float* __restrict__ B,
                                                  const float* __restrict__ D,
                                                  const float* __restrict__ L) {
    __shared__ float r_s[Nn];
    __shared__ float red[256];
    __shared__ float sres[10];
    int k = blockIdx.x;
    int tid = threadIdx.x;

    for (int i = tid; i < Nn; i += 256)
        r_s[i] = g_R[k][0][i] + g_R[k][1][i] + g_R[k][2][i] + g_R[k][3][i];
    __syncthreads();

    float acc[10];
    #pragma unroll
    for (int c = 0; c < 10; c++) acc[c] = 0.f;

    for (int i = tid; i < Nn; i += 256) {
        float rv = r_s[i];
        float4 b0 = *(const float4*)(B + i * INW);
        float4 b1 = *(const float4*)(B + i * INW + 4);
        acc[0] += rv * b0.x; acc[1] += rv * b0.y;
        acc[2] += rv * b0.z; acc[3] += rv * b0.w;
        acc[4] += rv * b1.x; acc[5] += rv * b1.y;
        acc[6] += rv * b1.z; acc[7] += rv * b1.w;
        acc[8] += rv * L[i];
        acc[9] += rv;                 // h0 = ones
    }

    #pragma unroll
    for (int c = 0; c < 10; c++) {
        red[tid] = acc[c];
        __syncthreads();
        for (int off = 128; off > 0; off >>= 1) {
            if (tid < off) red[tid] += red[tid + off];
            __syncthreads();
        }
        if (tid == 0) sres[c] = red[0];
        __syncthreads();
    }

    if (tid == 0) {
        float s = sres[8];
        #pragma unroll
        for (int c = 0; c < INW; c++) g_PQ[k][c] = sres[c] - s * D[c];
        g_PQ[k][8] = s;
        g_PQ[k][9] = sres[9];
    }
}

// ---------------------------------------------------------------------------
// conv: y_t = a_t + D.u_t + sum_{k<min(t,K)} [ p_k.u_{t-1-k} + q_k yobs_{t-1-k} ]
__global__ void __launch_bounds__(256) conv_kernel(const float* __restrict__ u,
                                                   const float* __restrict__ yobs,
                                                   const float* __restrict__ D,
                                                   float* __restrict__ out) {
    __shared__ float pq[K_TR][10];
    __shared__ float us[512][9];      // [local sidx][0..7]=u, [8]=yobs
    int tid = threadIdx.x;
    int t0  = blockIdx.x * 256;

    for (int idx = tid; idx < K_TR * 10; idx += 256)
        pq[idx / 10][idx % 10] = g_PQ[idx / 10][idx % 10];

    for (int l = tid; l < 512; l += 256) {
        int sidx = t0 - 256 + l;
        if (sidx >= 0 && sidx < Tt) {
            #pragma unroll
            for (int c = 0; c < INW; c++) us[l][c] = u[c * Tt + sidx];
            us[l][8] = yobs[sidx];
        } else {
            #pragma unroll
            for (int c = 0; c < 9; c++) us[l][c] = 0.f;
        }
    }
    __syncthreads();

    int t = t0 + tid;
    float y = 0.f;
    #pragma unroll
    for (int c = 0; c < INW; c++) y += D[c] * u[c * Tt + t];
    if (t < K_TR) y += pq[t][9];      // a_t = r_t . h0 (decayed ~0 beyond K)

    int kmax = min(t, K_TR);
    for (int kk = 0; kk < kmax; kk++) {
        int l = tid + 255 - kk;       // (t-1-kk) - (t0-256)
        float a = pq[kk][8] * us[l][8];
        #pragma unroll
        for (int c = 0; c < INW; c++) a += pq[kk][c] * us[l][c];
        y += a;
    }
    out[t] = 3.f * tanhf(y);
}

// ---------------------------------------------------------------------------
extern "C" void kernel_launch(void* const* d_in, const int* in_sizes, int n_in,
                              void* d_out, int out_size) {
    const float* u    = (const float*)d_in[0];  // [8,4096]
    const float* yobs = (const float*)d_in[1];  // [1,4096]
    const float* A    = (const float*)d_in[2];  // [4096,4096]
    const float* B    = (const float*)d_in[3];  // [4096,8]
    const float* C    = (const float*)d_in[4];  // [1,4096]
    const float* D    = (const float*)d_in[5];  // [1,8]
    const float* L    = (const float*)d_in[6];  // [4096,1]
    float* out = (float*)d_out;                 // [1,4096]
    (void)in_sizes; (void)n_in; (void)out_size;

    convert_kernel<<<(Nn * Nn / 4) / 256, 256>>>((const float4*)A);
    init_kernel<<<Nn / 256, 256>>>(C, L);
    step32_kernel<<<dim3(64, QP), 512>>>(0, 1, A, C, L);
    for (int k = 1; k < K_F32; k++)
        step32_kernel<<<dim3(64, QP), 512>>>(k, 256, A, C, L);
    steps_pers_kernel<<<NCTA, 512>>>(C, L);     // k = 8 .. K_TR-2
    phi_kernel<<<K_TR, 256>>>(B, D, L);
    conv_kernel<<<Tt / 256, 256>>>(u, yobs, D, out);
}

// round 12
// speedup vs baseline: 1.5460x; 1.3966x over previous
#include <cuda_runtime.h>
#include <cuda_fp16.h>
#include <cuda_fp8.h>
#include <math.h>

// StateNeuronSep: Luenberger observer, ORDER=4096, SEQ=4096, IN=8, OUT=1.
//
// y_t = r_t.h0 + sum_{k<t} [ (r_k B').u_{t-1-k} + (r_k L) yobs_{t-1-k} ] + D.u_t
// r_{k+1} = r_k A - (r_k.L) C   (row Krylov, rank-1 fold; M never materialized)
// Ladder: k in [0,8) fp32 | [8,48) fp16 | [48,88) fp8 e4m3 x2^14.  K=88.
// Proven R8 multi-launch structure: per-step kernels, QP partial planes,
// slice prologue, per-CTA s-partials in g_S (fixed-order sums, deterministic).

#define Nn 4096
#define Tt 4096
#define INW 8
#define K_TR 88
#define K_F32 8
#define FP8_START 48
#define QP 4
#define FP8_SCALE_INV 6.103515625e-05f   // 2^-14

// Scratch (device globals; no allocation allowed)
__device__ float   g_R[K_TR][QP][Nn];            // partial planes
__device__ float   g_S[K_TR][256];               // per-CTA partial s = r.L
__device__ float   g_PQ[K_TR][12];               // p[0..7], [8]=s_k, [9]=r_k.1
__device__ __half2 g_Ah[(Nn * Nn) / 2];          // 32 MB fp16 A
__device__ unsigned long long g_A8[(Nn * Nn) / 8];  // 16 MB fp8 (e4m3, x2^14) A

// ---------------------------------------------------------------------------
// one-time A (fp32) -> fp16 + scaled fp8.  4M float4 elements.
__global__ void __launch_bounds__(256) convert_kernel(const float4* __restrict__ A4) {
    int idx = blockIdx.x * 256 + threadIdx.x;      // 0 .. 4M-1
    float4 v = A4[idx];
    __half2 h0 = __floats2half2_rn(v.x, v.y);
    __half2 h1 = __floats2half2_rn(v.z, v.w);
    uint2 packed;
    packed.x = *reinterpret_cast<unsigned int*>(&h0);
    packed.y = *reinterpret_cast<unsigned int*>(&h1);
    ((uint2*)g_Ah)[idx] = packed;
    const float sc = 16384.f;                      // max |A|*2^14 ~ 399 < 448
    unsigned int b0 = __nv_cvt_float_to_fp8(v.x * sc, __NV_SATFINITE, __NV_E4M3);
    unsigned int b1 = __nv_cvt_float_to_fp8(v.y * sc, __NV_SATFINITE, __NV_E4M3);
    unsigned int b2 = __nv_cvt_float_to_fp8(v.z * sc, __NV_SATFINITE, __NV_E4M3);
    unsigned int b3 = __nv_cvt_float_to_fp8(v.w * sc, __NV_SATFINITE, __NV_E4M3);
    ((unsigned int*)g_A8)[idx] = b0 | (b1 << 8) | (b2 << 16) | (b3 << 24);
}

// ---------------------------------------------------------------------------
// init: r_0 = C in plane 0, zeros elsewhere; block 0 computes s_0 = C.L.
__global__ void init_kernel(const float* __restrict__ C,
                            const float* __restrict__ L) {
    __shared__ float red[256];
    int tid = threadIdx.x;
    int j = blockIdx.x * 256 + tid;
    if (j < Nn) {
        g_R[0][0][j] = C[j];
        g_R[0][1][j] = 0.f;
        g_R[0][2][j] = 0.f;
        g_R[0][3][j] = 0.f;
    }
    if (blockIdx.x == 0) {
        float sp = 0.f;
        for (int i = tid; i < Nn; i += 256) sp += C[i] * L[i];
        red[tid] = sp;
        __syncthreads();
        for (int off = 128; off > 0; off >>= 1) {
            if (tid < off) red[tid] += red[tid + off];
            __syncthreads();
        }
        if (tid == 0) g_S[0][0] = red[0];
    }
}

// ---------------------------------------------------------------------------
// Shared prologue: slice-assemble r_k (own row quarter, 1024 floats) and
// read s_k from the previous step's cnt partials (fixed order => deterministic).
#define PROLOGUE()                                                             \
    {                                                                          \
        if (tid < 256) {                                                       \
            const float4* p0 = (const float4*)&g_R[k][0][blockIdx.y * 1024];   \
            const float4* p1 = (const float4*)&g_R[k][1][blockIdx.y * 1024];   \
            const float4* p2 = (const float4*)&g_R[k][2][blockIdx.y * 1024];   \
            const float4* p3 = (const float4*)&g_R[k][3][blockIdx.y * 1024];   \
            float4 a = p0[tid], b = p1[tid], c = p2[tid], d = p3[tid];         \
            ((float4*)r_s)[tid] =                                              \
                make_float4(a.x + b.x + c.x + d.x, a.y + b.y + c.y + d.y,      \
                            a.z + b.z + c.z + d.z, a.w + b.w + c.w + d.w);     \
        } else if (tid >= 480) {                                               \
            int l2 = tid - 480;   /* one warp sums the s partials */           \
            float sp = 0.f;                                                    \
            for (int idx = l2; idx < cnt; idx += 32) sp += g_S[k][idx];        \
            _Pragma("unroll")                                                  \
            for (int off = 16; off > 0; off >>= 1)                             \
                sp += __shfl_xor_sync(0xffffffffu, sp, off);                   \
            if (l2 == 0) s_sh = sp;                                            \
        }                                                                      \
    }                                                                          \
    __syncthreads();

// Shared epilogue: reduce warp partials per column, fold -s*C on plane 0,
// write plane + per-CTA partial dot with L.
#define EPILOGUE(WIDTH, SCALE_EXPR)                                            \
    if (tid < (WIDTH)) {                                                       \
        float t = 0.f;                                                         \
        _Pragma("unroll")                                                      \
        for (int q = 0; q < 16; q++) t += acc_s[q][tid];                       \
        t = (SCALE_EXPR);                                                      \
        int j = colbase + tid;                                                 \
        if (blockIdx.y == 0) t -= s_sh * C[j];                                 \
        g_R[k + 1][blockIdx.y][j] = t;                                         \
        dot_s[tid] = t * L[j];                                                 \
    }                                                                          \
    __syncthreads();                                                           \
    for (int off = (WIDTH) / 2; off > 0; off >>= 1) {                          \
        if (tid < off) dot_s[tid] += dot_s[tid + off];                         \
        __syncthreads();                                                       \
    }                                                                          \
    if (tid == 0)                                                              \
        g_S[k + 1][blockIdx.y * gridDim.x + blockIdx.x] = dot_s[0];

// ---------------------------------------------------------------------------
// fp32 step: grid (64 col-tiles of 64, 4 row-quarters), block 512 (16 warps).
__global__ void __launch_bounds__(512) step32_kernel(int k, int cnt,
                                                     const float* __restrict__ A,
                                                     const float* __restrict__ C,
                                                     const float* __restrict__ L) {
    __shared__ __align__(16) float r_s[1024];   // own row-quarter slice
    __shared__ float acc_s[16][64];
    __shared__ float dot_s[64];
    __shared__ float s_sh;

    int tid  = threadIdx.x;
    int lane = tid & 31;
    int w    = tid >> 5;

    PROLOGUE()

    int colbase = blockIdx.x * 64;
    size_t c2   = (size_t)(colbase >> 1) + lane;
    int rowg    = blockIdx.y * 1024 + w * 64;   // global base row for this warp
    int il      = w * 64;                        // local base row in r_s

    const unsigned long long* Au = (const unsigned long long*)A;
    unsigned long long acc0 = 0ull, acc1 = 0ull;

    #pragma unroll 4
    for (int ii = 0; ii < 64; ii += 2) {
        float r0 = r_s[il + ii];
        float r1 = r_s[il + ii + 1];
        size_t gi = (size_t)(rowg + ii);
        unsigned long long a0 = Au[gi * (Nn / 2) + c2];
        unsigned long long a1 = Au[(gi + 1) * (Nn / 2) + c2];
        unsigned long long rr0, rr1;
        asm("mov.b64 %0, {%1, %1};" : "=l"(rr0) : "r"(__float_as_uint(r0)));
        asm("mov.b64 %0, {%1, %1};" : "=l"(rr1) : "r"(__float_as_uint(r1)));
        asm("fma.rn.f32x2 %0, %1, %2, %3;" : "=l"(acc0) : "l"(a0), "l"(rr0), "l"(acc0));
        asm("fma.rn.f32x2 %0, %1, %2, %3;" : "=l"(acc1) : "l"(a1), "l"(rr1), "l"(acc1));
    }
    unsigned long long accm;
    asm("add.rn.f32x2 %0, %1, %2;" : "=l"(accm) : "l"(acc0), "l"(acc1));
    unsigned int lo_u, hi_u;
    asm("mov.b64 {%0, %1}, %2;" : "=r"(lo_u), "=r"(hi_u) : "l"(accm));
    acc_s[w][lane * 2]     = __uint_as_float(lo_u);
    acc_s[w][lane * 2 + 1] = __uint_as_float(hi_u);
    __syncthreads();

    EPILOGUE(64, t)
}

// ---------------------------------------------------------------------------
// fp16 step: grid (32 col-tiles of 128, 4 row-quarters), block 512.
__global__ void __launch_bounds__(512) step16_kernel(int k, int cnt,
                                                     const float* __restrict__ C,
                                                     const float* __restrict__ L) {
    __shared__ __align__(16) float r_s[1024];
    __shared__ float acc_s[16][128];
    __shared__ float dot_s[128];
    __shared__ float s_sh;

    int tid  = threadIdx.x;
    int lane = tid & 31;
    int w    = tid >> 5;

    PROLOGUE()

    int colbase = blockIdx.x * 128;
    size_t c4   = (size_t)(colbase >> 2) + lane;   // u64 = 4 halves
    int rowg    = blockIdx.y * 1024 + w * 64;
    int il      = w * 64;

    const unsigned long long* Au = (const unsigned long long*)g_Ah;
    float a0 = 0.f, a1 = 0.f, a2 = 0.f, a3 = 0.f;

    #pragma unroll 4
    for (int ii = 0; ii < 64; ii++) {
        float rv = r_s[il + ii];
        unsigned long long av = Au[(size_t)(rowg + ii) * (Nn / 4) + c4];
        unsigned int lo = (unsigned int)av;
        unsigned int hi = (unsigned int)(av >> 32);
        float2 f0 = __half22float2(*(__half2*)&lo);
        float2 f1 = __half22float2(*(__half2*)&hi);
        a0 += rv * f0.x; a1 += rv * f0.y;
        a2 += rv * f1.x; a3 += rv * f1.y;
    }
    acc_s[w][lane * 4]     = a0;
    acc_s[w][lane * 4 + 1] = a1;
    acc_s[w][lane * 4 + 2] = a2;
    acc_s[w][lane * 4 + 3] = a3;
    __syncthreads();

    EPILOGUE(128, t)
}

// ---------------------------------------------------------------------------
// fp8 step: grid (32 col-tiles of 128, 4 row-quarters), block 512.
// Lane covers 8 cols (u64 = 8 e4m3); half-warps handle row parity.
__global__ void __launch_bounds__(512) step8_kernel(int k, int cnt,
                                                    const float* __restrict__ C,
                                                    const float* __restrict__ L) {
    __shared__ __align__(16) float r_s[1024];
    __shared__ float acc_s[16][128];
    __shared__ float dot_s[128];
    __shared__ float s_sh;

    int tid  = threadIdx.x;
    int lane = tid & 31;
    int w    = tid >> 5;

    PROLOGUE()

    int colbase = blockIdx.x * 128;
    int rowg    = blockIdx.y * 1024 + w * 64;
    int il      = w * 64;
    int half    = lane >> 4;                       // 0/1: row parity
    int lpos    = lane & 15;                       // col-group within tile
    size_t cu   = (size_t)(colbase >> 3) + lpos;   // u64 index within a row

    const unsigned long long* Au = g_A8;           // row = Nn/8 = 512 u64
    float acc[8];
    #pragma unroll
    for (int c = 0; c < 8; c++) acc[c] = 0.f;

    #pragma unroll 4
    for (int ii = 0; ii < 64; ii += 2) {
        float rv = r_s[il + ii + half];
        unsigned long long av = Au[(size_t)(rowg + ii + half) * (Nn / 8) + cu];
        unsigned short p0 = (unsigned short)av;
        unsigned short p1 = (unsigned short)(av >> 16);
        unsigned short p2 = (unsigned short)(av >> 32);
        unsigned short p3 = (unsigned short)(av >> 48);
        unsigned int h01, h23, h45, h67;
        asm("cvt.rn.f16x2.e4m3x2 %0, %1;" : "=r"(h01) : "h"(p0));
        asm("cvt.rn.f16x2.e4m3x2 %0, %1;" : "=r"(h23) : "h"(p1));
        asm("cvt.rn.f16x2.e4m3x2 %0, %1;" : "=r"(h45) : "h"(p2));
        asm("cvt.rn.f16x2.e4m3x2 %0, %1;" : "=r"(h67) : "h"(p3));
        float2 f0 = __half22float2(*(__half2*)&h01);
        float2 f1 = __half22float2(*(__half2*)&h23);
        float2 f2 = __half22float2(*(__half2*)&h45);
        float2 f3 = __half22float2(*(__half2*)&h67);
        acc[0] += rv * f0.x; acc[1] += rv * f0.y;
        acc[2] += rv * f1.x; acc[3] += rv * f1.y;
        acc[4] += rv * f2.x; acc[5] += rv * f2.y;
        acc[6] += rv * f3.x; acc[7] += rv * f3.y;
    }

    // fold the two row-parity half-warps (lanes 0..15 keep the sum)
    #pragma unroll
    for (int c = 0; c < 8; c++)
        acc[c] += __shfl_down_sync(0xffffffffu, acc[c], 16);
    if (lane < 16) {
        #pragma unroll
        for (int c = 0; c < 8; c++)
            acc_s[w][lpos * 8 + c] = acc[c];
    }
    __syncthreads();

    EPILOGUE(128, t * FP8_SCALE_INV)
}

// ---------------------------------------------------------------------------
// phi: p_k = r_k B - s_k D, q_k = s_k = r_k.L, a_k = r_k.1
__global__ void __launch_bounds__(256) phi_kernel(const float* __restrict__ B,
                                                  const float* __restrict__ D,
                                                  const float* __restrict__ L) {
    __shared__ float r_s[Nn];
    __shared__ float red[256];
    __shared__ float sres[10];
    int k = blockIdx.x;
    int tid = threadIdx.x;

    for (int i = tid; i < Nn; i += 256)
        r_s[i] = g_R[k][0][i] + g_R[k][1][i] + g_R[k][2][i] + g_R[k][3][i];
    __syncthreads();

    float acc[10];
    #pragma unroll
    for (int c = 0; c < 10; c++) acc[c] = 0.f;

    for (int i = tid; i < Nn; i += 256) {
        float rv = r_s[i];
        float4 b0 = *(const float4*)(B + i * INW);
        float4 b1 = *(const float4*)(B + i * INW + 4);
        acc[0] += rv * b0.x; acc[1] += rv * b0.y;
        acc[2] += rv * b0.z; acc[3] += rv * b0.w;
        acc[4] += rv * b1.x; acc[5] += rv * b1.y;
        acc[6] += rv * b1.z; acc[7] += rv * b1.w;
        acc[8] += rv * L[i];
        acc[9] += rv;                 // h0 = ones
    }

    #pragma unroll
    for (int c = 0; c < 10; c++) {
        red[tid] = acc[c];
        __syncthreads();
        for (int off = 128; off > 0; off >>= 1) {
            if (tid < off) red[tid] += red[tid + off];
            __syncthreads();
        }
        if (tid == 0) sres[c] = red[0];
        __syncthreads();
    }

    if (tid == 0) {
        float s = sres[8];
        #pragma unroll
        for (int c = 0; c < INW; c++) g_PQ[k][c] = sres[c] - s * D[c];
        g_PQ[k][8] = s;
        g_PQ[k][9] = sres[9];
    }
}

// ---------------------------------------------------------------------------
// conv: y_t = a_t + D.u_t + sum_{k<min(t,K)} [ p_k.u_{t-1-k} + q_k yobs_{t-1-k} ]
__global__ void __launch_bounds__(256) conv_kernel(const float* __restrict__ u,
                                                   const float* __restrict__ yobs,
                                                   const float* __restrict__ D,
                                                   float* __restrict__ out) {
    __shared__ float pq[K_TR][10];
    __shared__ float us[512][9];      // [local sidx][0..7]=u, [8]=yobs
    int tid = threadIdx.x;
    int t0  = blockIdx.x * 256;

    for (int idx = tid; idx < K_TR * 10; idx += 256)
        pq[idx / 10][idx % 10] = g_PQ[idx / 10][idx % 10];

    for (int l = tid; l < 512; l += 256) {
        int sidx = t0 - 256 + l;
        if (sidx >= 0 && sidx < Tt) {
            #pragma unroll
            for (int c = 0; c < INW; c++) us[l][c] = u[c * Tt + sidx];
            us[l][8] = yobs[sidx];
        } else {
            #pragma unroll
            for (int c = 0; c < 9; c++) us[l][c] = 0.f;
        }
    }
    __syncthreads();

    int t = t0 + tid;
    float y = 0.f;
    #pragma unroll
    for (int c = 0; c < INW; c++) y += D[c] * u[c * Tt + t];
    if (t < K_TR) y += pq[t][9];      // a_t = r_t . h0 (decayed ~0 beyond K)

    int kmax = min(t, K_TR);
    for (int kk = 0; kk < kmax; kk++) {
        int l = tid + 255 - kk;       // (t-1-kk) - (t0-256)
        float a = pq[kk][8] * us[l][8];
        #pragma unroll
        for (int c = 0; c < INW; c++) a += pq[kk][c] * us[l][c];
        y += a;
    }
    out[t] = 3.f * tanhf(y);
}

// ---------------------------------------------------------------------------
extern "C" void kernel_launch(void* const* d_in, const int* in_sizes, int n_in,
                              void* d_out, int out_size) {
    const float* u    = (const float*)d_in[0];  // [8,4096]
    const float* yobs = (const float*)d_in[1];  // [1,4096]
    const float* A    = (const float*)d_in[2];  // [4096,4096]
    const float* B    = (const float*)d_in[3];  // [4096,8]
    const float* C    = (const float*)d_in[4];  // [1,4096]
    const float* D    = (const float*)d_in[5];  // [1,8]
    const float* L    = (const float*)d_in[6];  // [4096,1]
    float* out = (float*)d_out;                 // [1,4096]
    (void)in_sizes; (void)n_in; (void)out_size;

    convert_kernel<<<(Nn * Nn / 4) / 256, 256>>>((const float4*)A);
    init_kernel<<<Nn / 256, 256>>>(C, L);
    step32_kernel<<<dim3(64, QP), 512>>>(0, 1, A, C, L);
    for (int k = 1; k < K_F32; k++)
        step32_kernel<<<dim3(64, QP), 512>>>(k, 256, A, C, L);
    step16_kernel<<<dim3(32, QP), 512>>>(K_F32, 256, C, L);
    for (int k = K_F32 + 1; k < FP8_START; k++)
        step16_kernel<<<dim3(32, QP), 512>>>(k, 128, C, L);
    for (int k = FP8_START; k < K_TR - 1; k++)
        step8_kernel<<<dim3(32, QP), 512>>>(k, 128, C, L);
    phi_kernel<<<K_TR, 256>>>(B, D, L);
    conv_kernel<<<Tt / 256, 256>>>(u, yobs, D, out);
}

// round 13
// speedup vs baseline: 1.7597x; 1.1382x over previous
#include <cuda_runtime.h>
#include <cuda_fp16.h>
#include <cuda_fp8.h>
#include <math.h>

// StateNeuronSep: Luenberger observer, ORDER=4096, SEQ=4096, IN=8, OUT=1.
//
// y_t = r_t.h0 + sum_{k<t} [ (r_k B').u_{t-1-k} + (r_k L) yobs_{t-1-k} ] + D.u_t
// r_{k+1} = r_k A - (r_k.L) C   (row Krylov, rank-1 fold; M never materialized)
// Ladder: k in [0,8) fp32 (streamed, evict-first) | [8,48) fp16 | [48,72) fp8.
// fp32 A is read with __ldcs so its 64 MB never pollutes L2 — the fp16 (32 MB)
// + fp8 (16 MB) copies stay L2-resident across their step phases.

#define Nn 4096
#define Tt 4096
#define INW 8
#define K_TR 72
#define K_F32 8
#define FP8_START 48
#define QP 4
#define FP8_SCALE_INV 6.103515625e-05f   // 2^-14

// Scratch (device globals; no allocation allowed)
__device__ float   g_R[K_TR][QP][Nn];            // partial planes
__device__ float   g_S[K_TR][256];               // per-CTA partial s = r.L
__device__ float   g_PQ[K_TR][12];               // p[0..7], [8]=s_k, [9]=r_k.1
__device__ __half2 g_Ah[(Nn * Nn) / 2];          // 32 MB fp16 A
__device__ unsigned long long g_A8[(Nn * Nn) / 8];  // 16 MB fp8 (e4m3, x2^14) A

// ---------------------------------------------------------------------------
// one-time A (fp32) -> fp16 + scaled fp8.  4M float4 elements.
// A read via __ldcs (streaming) — used once here + 8 fp32 steps; keep out of L2.
__global__ void __launch_bounds__(256) convert_kernel(const float4* __restrict__ A4) {
    int idx = blockIdx.x * 256 + threadIdx.x;      // 0 .. 4M-1
    float4 v = __ldcs(A4 + idx);
    __half2 h0 = __floats2half2_rn(v.x, v.y);
    __half2 h1 = __floats2half2_rn(v.z, v.w);
    uint2 packed;
    packed.x = *reinterpret_cast<unsigned int*>(&h0);
    packed.y = *reinterpret_cast<unsigned int*>(&h1);
    ((uint2*)g_Ah)[idx] = packed;
    const float sc = 16384.f;                      // max |A|*2^14 ~ 399 < 448
    unsigned int b0 = __nv_cvt_float_to_fp8(v.x * sc, __NV_SATFINITE, __NV_E4M3);
    unsigned int b1 = __nv_cvt_float_to_fp8(v.y * sc, __NV_SATFINITE, __NV_E4M3);
    unsigned int b2 = __nv_cvt_float_to_fp8(v.z * sc, __NV_SATFINITE, __NV_E4M3);
    unsigned int b3 = __nv_cvt_float_to_fp8(v.w * sc, __NV_SATFINITE, __NV_E4M3);
    ((unsigned int*)g_A8)[idx] = b0 | (b1 << 8) | (b2 << 16) | (b3 << 24);
}

// ---------------------------------------------------------------------------
// init: r_0 = C in plane 0, zeros elsewhere; block 0 computes s_0 = C.L.
__global__ void init_kernel(const float* __restrict__ C,
                            const float* __restrict__ L) {
    __shared__ float red[256];
    int tid = threadIdx.x;
    int j = blockIdx.x * 256 + tid;
    if (j < Nn) {
        g_R[0][0][j] = C[j];
        g_R[0][1][j] = 0.f;
        g_R[0][2][j] = 0.f;
        g_R[0][3][j] = 0.f;
    }
    if (blockIdx.x == 0) {
        float sp = 0.f;
        for (int i = tid; i < Nn; i += 256) sp += C[i] * L[i];
        red[tid] = sp;
        __syncthreads();
        for (int off = 128; off > 0; off >>= 1) {
            if (tid < off) red[tid] += red[tid + off];
            __syncthreads();
        }
        if (tid == 0) g_S[0][0] = red[0];
    }
}

// ---------------------------------------------------------------------------
// Shared prologue: slice-assemble r_k (own row quarter, 1024 floats) and
// read s_k from the previous step's cnt partials (fixed order => deterministic).
#define PROLOGUE()                                                             \
    {                                                                          \
        if (tid < 256) {                                                       \
            const float4* p0 = (const float4*)&g_R[k][0][blockIdx.y * 1024];   \
            const float4* p1 = (const float4*)&g_R[k][1][blockIdx.y * 1024];   \
            const float4* p2 = (const float4*)&g_R[k][2][blockIdx.y * 1024];   \
            const float4* p3 = (const float4*)&g_R[k][3][blockIdx.y * 1024];   \
            float4 a = p0[tid], b = p1[tid], c = p2[tid], d = p3[tid];         \
            ((float4*)r_s)[tid] =                                              \
                make_float4(a.x + b.x + c.x + d.x, a.y + b.y + c.y + d.y,      \
                            a.z + b.z + c.z + d.z, a.w + b.w + c.w + d.w);     \
        } else if (tid >= 480) {                                               \
            int l2 = tid - 480;   /* one warp sums the s partials */           \
            float sp = 0.f;                                                    \
            for (int idx = l2; idx < cnt; idx += 32) sp += g_S[k][idx];        \
            _Pragma("unroll")                                                  \
            for (int off = 16; off > 0; off >>= 1)                             \
                sp += __shfl_xor_sync(0xffffffffu, sp, off);                   \
            if (l2 == 0) s_sh = sp;                                            \
        }                                                                      \
    }                                                                          \
    __syncthreads();

// Shared epilogue: reduce warp partials per column, fold -s*C on plane 0,
// write plane + per-CTA partial dot with L.
#define EPILOGUE(WIDTH, SCALE_EXPR)                                            \
    if (tid < (WIDTH)) {                                                       \
        float t = 0.f;                                                         \
        _Pragma("unroll")                                                      \
        for (int q = 0; q < 16; q++) t += acc_s[q][tid];                       \
        t = (SCALE_EXPR);                                                      \
        int j = colbase + tid;                                                 \
        if (blockIdx.y == 0) t -= s_sh * C[j];                                 \
        g_R[k + 1][blockIdx.y][j] = t;                                         \
        dot_s[tid] = t * L[j];                                                 \
    }                                                                          \
    __syncthreads();                                                           \
    for (int off = (WIDTH) / 2; off > 0; off >>= 1) {                          \
        if (tid < off) dot_s[tid] += dot_s[tid + off];                         \
        __syncthreads();                                                       \
    }                                                                          \
    if (tid == 0)                                                              \
        g_S[k + 1][blockIdx.y * gridDim.x + blockIdx.x] = dot_s[0];

// ---------------------------------------------------------------------------
// fp32 step: grid (64 col-tiles of 64, 4 row-quarters), block 512 (16 warps).
// A loads use __ldcs (evict-first) — read 8x total, keep L2 for fp16/fp8 copies.
__global__ void __launch_bounds__(512) step32_kernel(int k, int cnt,
                                                     const float* __restrict__ A,
                                                     const float* __restrict__ C,
                                                     const float* __restrict__ L) {
    __shared__ __align__(16) float r_s[1024];   // own row-quarter slice
    __shared__ float acc_s[16][64];
    __shared__ float dot_s[64];
    __shared__ float s_sh;

    int tid  = threadIdx.x;
    int lane = tid & 31;
    int w    = tid >> 5;

    PROLOGUE()

    int colbase = blockIdx.x * 64;
    size_t c2   = (size_t)(colbase >> 1) + lane;
    int rowg    = blockIdx.y * 1024 + w * 64;   // global base row for this warp
    int il      = w * 64;                        // local base row in r_s

    const unsigned long long* Au = (const unsigned long long*)A;
    unsigned long long acc0 = 0ull, acc1 = 0ull;

    #pragma unroll 4
    for (int ii = 0; ii < 64; ii += 2) {
        float r0 = r_s[il + ii];
        float r1 = r_s[il + ii + 1];
        size_t gi = (size_t)(rowg + ii);
        unsigned long long a0 = __ldcs(Au + gi * (Nn / 2) + c2);
        unsigned long long a1 = __ldcs(Au + (gi + 1) * (Nn / 2) + c2);
        unsigned long long rr0, rr1;
        asm("mov.b64 %0, {%1, %1};" : "=l"(rr0) : "r"(__float_as_uint(r0)));
        asm("mov.b64 %0, {%1, %1};" : "=l"(rr1) : "r"(__float_as_uint(r1)));
        asm("fma.rn.f32x2 %0, %1, %2, %3;" : "=l"(acc0) : "l"(a0), "l"(rr0), "l"(acc0));
        asm("fma.rn.f32x2 %0, %1, %2, %3;" : "=l"(acc1) : "l"(a1), "l"(rr1), "l"(acc1));
    }
    unsigned long long accm;
    asm("add.rn.f32x2 %0, %1, %2;" : "=l"(accm) : "l"(acc0), "l"(acc1));
    unsigned int lo_u, hi_u;
    asm("mov.b64 {%0, %1}, %2;" : "=r"(lo_u), "=r"(hi_u) : "l"(accm));
    acc_s[w][lane * 2]     = __uint_as_float(lo_u);
    acc_s[w][lane * 2 + 1] = __uint_as_float(hi_u);
    __syncthreads();

    EPILOGUE(64, t)
}

// ---------------------------------------------------------------------------
// fp16 step: grid (32 col-tiles of 128, 4 row-quarters), block 512.
__global__ void __launch_bounds__(512) step16_kernel(int k, int cnt,
                                                     const float* __restrict__ C,
                                                     const float* __restrict__ L) {
    __shared__ __align__(16) float r_s[1024];
    __shared__ float acc_s[16][128];
    __shared__ float dot_s[128];
    __shared__ float s_sh;

    int tid  = threadIdx.x;
    int lane = tid & 31;
    int w    = tid >> 5;

    PROLOGUE()

    int colbase = blockIdx.x * 128;
    size_t c4   = (size_t)(colbase >> 2) + lane;   // u64 = 4 halves
    int rowg    = blockIdx.y * 1024 + w * 64;
    int il      = w * 64;

    const unsigned long long* Au = (const unsigned long long*)g_Ah;
    float a0 = 0.f, a1 = 0.f, a2 = 0.f, a3 = 0.f;

    #pragma unroll 4
    for (int ii = 0; ii < 64; ii++) {
        float rv = r_s[il + ii];
        unsigned long long av = Au[(size_t)(rowg + ii) * (Nn / 4) + c4];
        unsigned int lo = (unsigned int)av;
        unsigned int hi = (unsigned int)(av >> 32);
        float2 f0 = __half22float2(*(__half2*)&lo);
        float2 f1 = __half22float2(*(__half2*)&hi);
        a0 += rv * f0.x; a1 += rv * f0.y;
        a2 += rv * f1.x; a3 += rv * f1.y;
    }
    acc_s[w][lane * 4]     = a0;
    acc_s[w][lane * 4 + 1] = a1;
    acc_s[w][lane * 4 + 2] = a2;
    acc_s[w][lane * 4 + 3] = a3;
    __syncthreads();

    EPILOGUE(128, t)
}

// ---------------------------------------------------------------------------
// fp8 step: grid (32 col-tiles of 128, 4 row-quarters), block 512.
// Lane covers 8 cols (u64 = 8 e4m3); half-warps handle row parity.
__global__ void __launch_bounds__(512) step8_kernel(int k, int cnt,
                                                    const float* __restrict__ C,
                                                    const float* __restrict__ L) {
    __shared__ __align__(16) float r_s[1024];
    __shared__ float acc_s[16][128];
    __shared__ float dot_s[128];
    __shared__ float s_sh;

    int tid  = threadIdx.x;
    int lane = tid & 31;
    int w    = tid >> 5;

    PROLOGUE()

    int colbase = blockIdx.x * 128;
    int rowg    = blockIdx.y * 1024 + w * 64;
    int il      = w * 64;
    int half    = lane >> 4;                       // 0/1: row parity
    int lpos    = lane & 15;                       // col-group within tile
    size_t cu   = (size_t)(colbase >> 3) + lpos;   // u64 index within a row

    const unsigned long long* Au = g_A8;           // row = Nn/8 = 512 u64
    float acc[8];
    #pragma unroll
    for (int c = 0; c < 8; c++) acc[c] = 0.f;

    #pragma unroll 4
    for (int ii = 0; ii < 64; ii += 2) {
        float rv = r_s[il + ii + half];
        unsigned long long av = Au[(size_t)(rowg + ii + half) * (Nn / 8) + cu];
        unsigned short p0 = (unsigned short)av;
        unsigned short p1 = (unsigned short)(av >> 16);
        unsigned short p2 = (unsigned short)(av >> 32);
        unsigned short p3 = (unsigned short)(av >> 48);
        unsigned int h01, h23, h45, h67;
        asm("cvt.rn.f16x2.e4m3x2 %0, %1;" : "=r"(h01) : "h"(p0));
        asm("cvt.rn.f16x2.e4m3x2 %0, %1;" : "=r"(h23) : "h"(p1));
        asm("cvt.rn.f16x2.e4m3x2 %0, %1;" : "=r"(h45) : "h"(p2));
        asm("cvt.rn.f16x2.e4m3x2 %0, %1;" : "=r"(h67) : "h"(p3));
        float2 f0 = __half22float2(*(__half2*)&h01);
        float2 f1 = __half22float2(*(__half2*)&h23);
        float2 f2 = __half22float2(*(__half2*)&h45);
        float2 f3 = __half22float2(*(__half2*)&h67);
        acc[0] += rv * f0.x; acc[1] += rv * f0.y;
        acc[2] += rv * f1.x; acc[3] += rv * f1.y;
        acc[4] += rv * f2.x; acc[5] += rv * f2.y;
        acc[6] += rv * f3.x; acc[7] += rv * f3.y;
    }

    // fold the two row-parity half-warps (lanes 0..15 keep the sum)
    #pragma unroll
    for (int c = 0; c < 8; c++)
        acc[c] += __shfl_down_sync(0xffffffffu, acc[c], 16);
    if (lane < 16) {
        #pragma unroll
        for (int c = 0; c < 8; c++)
            acc_s[w][lpos * 8 + c] = acc[c];
    }
    __syncthreads();

    EPILOGUE(128, t * FP8_SCALE_INV)
}

// ---------------------------------------------------------------------------
// phi: p_k = r_k B - s_k D, q_k = s_k = r_k.L, a_k = r_k.1
__global__ void __launch_bounds__(256) phi_kernel(const float* __restrict__ B,
                                                  const float* __restrict__ D,
                                                  const float* __restrict__ L) {
    __shared__ float r_s[Nn];
    __shared__ float red[256];
    __shared__ float sres[10];
    int k = blockIdx.x;
    int tid = threadIdx.x;

    for (int i = tid; i < Nn; i += 256)
        r_s[i] = g_R[k][0][i] + g_R[k][1][i] + g_R[k][2][i] + g_R[k][3][i];
    __syncthreads();

    float acc[10];
    #pragma unroll
    for (int c = 0; c < 10; c++) acc[c] = 0.f;

    for (int i = tid; i < Nn; i += 256) {
        float rv = r_s[i];
        float4 b0 = *(const float4*)(B + i * INW);
        float4 b1 = *(const float4*)(B + i * INW + 4);
        acc[0] += rv * b0.x; acc[1] += rv * b0.y;
        acc[2] += rv * b0.z; acc[3] += rv * b0.w;
        acc[4] += rv * b1.x; acc[5] += rv * b1.y;
        acc[6] += rv * b1.z; acc[7] += rv * b1.w;
        acc[8] += rv * L[i];
        acc[9] += rv;                 // h0 = ones
    }

    #pragma unroll
    for (int c = 0; c < 10; c++) {
        red[tid] = acc[c];
        __syncthreads();
        for (int off = 128; off > 0; off >>= 1) {
            if (tid < off) red[tid] += red[tid + off];
            __syncthreads();
        }
        if (tid == 0) sres[c] = red[0];
        __syncthreads();
    }

    if (tid == 0) {
        float s = sres[8];
        #pragma unroll
        for (int c = 0; c < INW; c++) g_PQ[k][c] = sres[c] - s * D[c];
        g_PQ[k][8] = s;
        g_PQ[k][9] = sres[9];
    }
}

// ---------------------------------------------------------------------------
// conv: y_t = a_t + D.u_t + sum_{k<min(t,K)} [ p_k.u_{t-1-k} + q_k yobs_{t-1-k} ]
__global__ void __launch_bounds__(256) conv_kernel(const float* __restrict__ u,
                                                   const float* __restrict__ yobs,
                                                   const float* __restrict__ D,
                                                   float* __restrict__ out) {
    __shared__ float pq[K_TR][10];
    __shared__ float us[512][9];      // [local sidx][0..7]=u, [8]=yobs
    int tid = threadIdx.x;
    int t0  = blockIdx.x * 256;

    for (int idx = tid; idx < K_TR * 10; idx += 256)
        pq[idx / 10][idx % 10] = g_PQ[idx / 10][idx % 10];

    for (int l = tid; l < 512; l += 256) {
        int sidx = t0 - 256 + l;
        if (sidx >= 0 && sidx < Tt) {
            #pragma unroll
            for (int c = 0; c < INW; c++) us[l][c] = u[c * Tt + sidx];
            us[l][8] = yobs[sidx];
        } else {
            #pragma unroll
            for (int c = 0; c < 9; c++) us[l][c] = 0.f;
        }
    }
    __syncthreads();

    int t = t0 + tid;
    float y = 0.f;
    #pragma unroll
    for (int c = 0; c < INW; c++) y += D[c] * u[c * Tt + t];
    if (t < K_TR) y += pq[t][9];      // a_t = r_t . h0 (decayed ~0 beyond K)

    int kmax = min(t, K_TR);
    for (int kk = 0; kk < kmax; kk++) {
        int l = tid + 255 - kk;       // (t-1-kk) - (t0-256)
        float a = pq[kk][8] * us[l][8];
        #pragma unroll
        for (int c = 0; c < INW; c++) a += pq[kk][c] * us[l][c];
        y += a;
    }
    out[t] = 3.f * tanhf(y);
}

// ---------------------------------------------------------------------------
extern "C" void kernel_launch(void* const* d_in, const int* in_sizes, int n_in,
                              void* d_out, int out_size) {
    const float* u    = (const float*)d_in[0];  // [8,4096]
    const float* yobs = (const float*)d_in[1];  // [1,4096]
    const float* A    = (const float*)d_in[2];  // [4096,4096]
    const float* B    = (const float*)d_in[3];  // [4096,8]
    const float* C    = (const float*)d_in[4];  // [1,4096]
    const float* D    = (const float*)d_in[5];  // [1,8]
    const float* L    = (const float*)d_in[6];  // [4096,1]
    float* out = (float*)d_out;                 // [1,4096]
    (void)in_sizes; (void)n_in; (void)out_size;

    convert_kernel<<<(Nn * Nn / 4) / 256, 256>>>((const float4*)A);
    init_kernel<<<Nn / 256, 256>>>(C, L);
    step32_kernel<<<dim3(64, QP), 512>>>(0, 1, A, C, L);
    for (int k = 1; k < K_F32; k++)
        step32_kernel<<<dim3(64, QP), 512>>>(k, 256, A, C, L);
    step16_kernel<<<dim3(32, QP), 512>>>(K_F32, 256, C, L);
    for (int k = K_F32 + 1; k < FP8_START; k++)
        step16_kernel<<<dim3(32, QP), 512>>>(k, 128, C, L);
    for (int k = FP8_START; k < K_TR - 1; k++)
        step8_kernel<<<dim3(32, QP), 512>>>(k, 128, C, L);
    phi_kernel<<<K_TR, 256>>>(B, D, L);
    conv_kernel<<<Tt / 256, 256>>>(u, yobs, D, out);
}

// round 14
// speedup vs baseline: 1.8830x; 1.0701x over previous
#include <cuda_runtime.h>
#include <cuda_fp16.h>
#include <cuda_fp8.h>
#include <math.h>

// StateNeuronSep: Luenberger observer, ORDER=4096, SEQ=4096, IN=8, OUT=1.
//
// y_t = r_t.h0 + sum_{k<t} [ (r_k B').u_{t-1-k} + (r_k L) yobs_{t-1-k} ] + D.u_t
// r_{k+1} = r_k A - (r_k.L) C   (row Krylov, rank-1 fold; M never materialized)
// Ladder: k in [0,8)  fp16 + fp8-residual (A ~ A16 + E8*2^-24, ~fp23 accuracy)
//         k in [8,48) fp16 | [48,72) fp8 e4m3 x2^14.   K = 72.
// fp32 A is read exactly ONCE (convert, streaming). Working set in L2:
// fp16 32MB + residual 16MB + fp8 16MB = 64MB < 126MB -> no thrash.

#define Nn 4096
#define Tt 4096
#define INW 8
#define K_TR 72
#define K_F16R 8
#define FP8_START 48
#define QP 4
#define FP8_SCALE_INV 6.103515625e-05f    // 2^-14
#define RES_SCALE     16777216.f          // 2^24
#define RES_SCALE_INV 5.9604644775390625e-08f  // 2^-24

// Scratch (device globals; no allocation allowed)
__device__ float   g_R[K_TR][QP][Nn];            // partial planes
__device__ float   g_S[K_TR][256];               // per-CTA partial s = r.L
__device__ float   g_PQ[K_TR][12];               // p[0..7], [8]=s_k, [9]=r_k.1
__device__ __half2 g_Ah[(Nn * Nn) / 2];          // 32 MB fp16 A
__device__ unsigned long long g_A8[(Nn * Nn) / 8];  // 16 MB fp8 (e4m3, x2^14) A
__device__ unsigned long long g_E8[(Nn * Nn) / 8];  // 16 MB fp8 residual (x2^24)

// ---------------------------------------------------------------------------
// one-time A (fp32, streamed) -> fp16 + fp8 + fp8-residual.  4M float4 elems.
__global__ void __launch_bounds__(256) convert_kernel(const float4* __restrict__ A4) {
    int idx = blockIdx.x * 256 + threadIdx.x;      // 0 .. 4M-1
    float4 v = __ldcs(A4 + idx);
    __half2 h0 = __floats2half2_rn(v.x, v.y);
    __half2 h1 = __floats2half2_rn(v.z, v.w);
    uint2 packed;
    packed.x = *reinterpret_cast<unsigned int*>(&h0);
    packed.y = *reinterpret_cast<unsigned int*>(&h1);
    ((uint2*)g_Ah)[idx] = packed;
    // fp8 e4m3, scaled by 2^14 (max |A|*2^14 ~ 399 < 448)
    const float sc = 16384.f;
    unsigned int b0 = __nv_cvt_float_to_fp8(v.x * sc, __NV_SATFINITE, __NV_E4M3);
    unsigned int b1 = __nv_cvt_float_to_fp8(v.y * sc, __NV_SATFINITE, __NV_E4M3);
    unsigned int b2 = __nv_cvt_float_to_fp8(v.z * sc, __NV_SATFINITE, __NV_E4M3);
    unsigned int b3 = __nv_cvt_float_to_fp8(v.w * sc, __NV_SATFINITE, __NV_E4M3);
    ((unsigned int*)g_A8)[idx] = b0 | (b1 << 8) | (b2 << 16) | (b3 << 24);
    // residual E = A - fp16(A), scaled 2^24 (|E|*2^24 <= ~256 < 448)
    float2 f0 = __half22float2(h0);
    float2 f1 = __half22float2(h1);
    unsigned int e0 = __nv_cvt_float_to_fp8((v.x - f0.x) * RES_SCALE, __NV_SATFINITE, __NV_E4M3);
    unsigned int e1 = __nv_cvt_float_to_fp8((v.y - f0.y) * RES_SCALE, __NV_SATFINITE, __NV_E4M3);
    unsigned int e2 = __nv_cvt_float_to_fp8((v.z - f1.x) * RES_SCALE, __NV_SATFINITE, __NV_E4M3);
    unsigned int e3 = __nv_cvt_float_to_fp8((v.w - f1.y) * RES_SCALE, __NV_SATFINITE, __NV_E4M3);
    ((unsigned int*)g_E8)[idx] = e0 | (e1 << 8) | (e2 << 16) | (e3 << 24);
}

// ---------------------------------------------------------------------------
// init: r_0 = C in plane 0, zeros elsewhere; block 0 computes s_0 = C.L.
__global__ void init_kernel(const float* __restrict__ C,
                            const float* __restrict__ L) {
    __shared__ float red[256];
    int tid = threadIdx.x;
    int j = blockIdx.x * 256 + tid;
    if (j < Nn) {
        g_R[0][0][j] = C[j];
        g_R[0][1][j] = 0.f;
        g_R[0][2][j] = 0.f;
        g_R[0][3][j] = 0.f;
    }
    if (blockIdx.x == 0) {
        float sp = 0.f;
        for (int i = tid; i < Nn; i += 256) sp += C[i] * L[i];
        red[tid] = sp;
        __syncthreads();
        for (int off = 128; off > 0; off >>= 1) {
            if (tid < off) red[tid] += red[tid + off];
            __syncthreads();
        }
        if (tid == 0) g_S[0][0] = red[0];
    }
}

// ---------------------------------------------------------------------------
// Shared prologue: slice-assemble r_k (own row quarter, 1024 floats) and
// read s_k from the previous step's cnt partials (fixed order => deterministic).
#define PROLOGUE()                                                             \
    {                                                                          \
        if (tid < 256) {                                                       \
            const float4* p0 = (const float4*)&g_R[k][0][blockIdx.y * 1024];   \
            const float4* p1 = (const float4*)&g_R[k][1][blockIdx.y * 1024];   \
            const float4* p2 = (const float4*)&g_R[k][2][blockIdx.y * 1024];   \
            const float4* p3 = (const float4*)&g_R[k][3][blockIdx.y * 1024];   \
            float4 a = p0[tid], b = p1[tid], c = p2[tid], d = p3[tid];         \
            ((float4*)r_s)[tid] =                                              \
                make_float4(a.x + b.x + c.x + d.x, a.y + b.y + c.y + d.y,      \
                            a.z + b.z + c.z + d.z, a.w + b.w + c.w + d.w);     \
        } else if (tid >= 480) {                                               \
            int l2 = tid - 480;   /* one warp sums the s partials */           \
            float sp = 0.f;                                                    \
            for (int idx = l2; idx < cnt; idx += 32) sp += g_S[k][idx];        \
            _Pragma("unroll")                                                  \
            for (int off = 16; off > 0; off >>= 1)                             \
                sp += __shfl_xor_sync(0xffffffffu, sp, off);                   \
            if (l2 == 0) s_sh = sp;                                            \
        }                                                                      \
    }                                                                          \
    __syncthreads();

// Shared epilogue: reduce warp partials per column, fold -s*C on plane 0,
// write plane + per-CTA partial dot with L.
#define EPILOGUE(WIDTH, SCALE_EXPR)                                            \
    if (tid < (WIDTH)) {                                                       \
        float t = 0.f;                                                         \
        _Pragma("unroll")                                                      \
        for (int q = 0; q < 16; q++) t += acc_s[q][tid];                       \
        t = (SCALE_EXPR);                                                      \
        int j = colbase + tid;                                                 \
        if (blockIdx.y == 0) t -= s_sh * C[j];                                 \
        g_R[k + 1][blockIdx.y][j] = t;                                         \
        dot_s[tid] = t * L[j];                                                 \
    }                                                                          \
    __syncthreads();                                                           \
    for (int off = (WIDTH) / 2; off > 0; off >>= 1) {                          \
        if (tid < off) dot_s[tid] += dot_s[tid + off];                         \
        __syncthreads();                                                       \
    }                                                                          \
    if (tid == 0)                                                              \
        g_S[k + 1][blockIdx.y * gridDim.x + blockIdx.x] = dot_s[0];

// ---------------------------------------------------------------------------
// fp16 + fp8-residual step (~fp23 accuracy): grid (32 col-tiles of 128,
// 4 row-quarters), block 512. Lane covers 8 cols; half-warps on row parity.
// val = a16 + e * 2^-24 per element; reads 48 MB from L2.
__global__ void __launch_bounds__(512) step16r_kernel(int k, int cnt,
                                                      const float* __restrict__ C,
                                                      const float* __restrict__ L) {
    __shared__ __align__(16) float r_s[1024];
    __shared__ float acc_s[16][128];
    __shared__ float dot_s[128];
    __shared__ float s_sh;

    int tid  = threadIdx.x;
    int lane = tid & 31;
    int w    = tid >> 5;

    PROLOGUE()

    int colbase = blockIdx.x * 128;
    int rowg    = blockIdx.y * 1024 + w * 64;
    int il      = w * 64;
    int half    = lane >> 4;                        // 0/1: row parity
    int lpos    = lane & 15;                        // col-group within tile
    size_t c16  = (size_t)(colbase >> 2) + lpos * 2; // fp16 u64 pair base
    size_t cuE  = (size_t)(colbase >> 3) + lpos;     // residual u64 per row

    const unsigned long long* A16u = (const unsigned long long*)g_Ah;
    const unsigned long long* E8u  = g_E8;

    float acc[8];
    #pragma unroll
    for (int c = 0; c < 8; c++) acc[c] = 0.f;

    #pragma unroll 4
    for (int ii = 0; ii < 64; ii += 2) {
        int gr = rowg + ii + half;
        float rv = r_s[il + ii + half];
        unsigned long long a01 = A16u[(size_t)gr * (Nn / 4) + c16];
        unsigned long long a23 = A16u[(size_t)gr * (Nn / 4) + c16 + 1];
        unsigned long long ev  = E8u[(size_t)gr * (Nn / 8) + cuE];
        // fp16 values (8 cols)
        unsigned int u0 = (unsigned int)a01, u1 = (unsigned int)(a01 >> 32);
        unsigned int u2 = (unsigned int)a23, u3 = (unsigned int)(a23 >> 32);
        float2 f0 = __half22float2(*(__half2*)&u0);
        float2 f1 = __half22float2(*(__half2*)&u1);
        float2 f2 = __half22float2(*(__half2*)&u2);
        float2 f3 = __half22float2(*(__half2*)&u3);
        // residuals (8 cols)
        unsigned short p0 = (unsigned short)ev;
        unsigned short p1 = (unsigned short)(ev >> 16);
        unsigned short p2 = (unsigned short)(ev >> 32);
        unsigned short p3 = (unsigned short)(ev >> 48);
        unsigned int h01, h23, h45, h67;
        asm("cvt.rn.f16x2.e4m3x2 %0, %1;" : "=r"(h01) : "h"(p0));
        asm("cvt.rn.f16x2.e4m3x2 %0, %1;" : "=r"(h23) : "h"(p1));
        asm("cvt.rn.f16x2.e4m3x2 %0, %1;" : "=r"(h45) : "h"(p2));
        asm("cvt.rn.f16x2.e4m3x2 %0, %1;" : "=r"(h67) : "h"(p3));
        float2 e0 = __half22float2(*(__half2*)&h01);
        float2 e1 = __half22float2(*(__half2*)&h23);
        float2 e2 = __half22float2(*(__half2*)&h45);
        float2 e3 = __half22float2(*(__half2*)&h67);
        acc[0] += rv * fmaf(e0.x, RES_SCALE_INV, f0.x);
        acc[1] += rv * fmaf(e0.y, RES_SCALE_INV, f0.y);
        acc[2] += rv * fmaf(e1.x, RES_SCALE_INV, f1.x);
        acc[3] += rv * fmaf(e1.y, RES_SCALE_INV, f1.y);
        acc[4] += rv * fmaf(e2.x, RES_SCALE_INV, f2.x);
        acc[5] += rv * fmaf(e2.y, RES_SCALE_INV, f2.y);
        acc[6] += rv * fmaf(e3.x, RES_SCALE_INV, f3.x);
        acc[7] += rv * fmaf(e3.y, RES_SCALE_INV, f3.y);
    }

    // fold the two row-parity half-warps (lanes 0..15 keep the sum)
    #pragma unroll
    for (int c = 0; c < 8; c++)
        acc[c] += __shfl_down_sync(0xffffffffu, acc[c], 16);
    if (lane < 16) {
        #pragma unroll
        for (int c = 0; c < 8; c++)
            acc_s[w][lpos * 8 + c] = acc[c];
    }
    __syncthreads();

    EPILOGUE(128, t)
}

// ---------------------------------------------------------------------------
// fp16 step: grid (32 col-tiles of 128, 4 row-quarters), block 512.
__global__ void __launch_bounds__(512) step16_kernel(int k, int cnt,
                                                     const float* __restrict__ C,
                                                     const float* __restrict__ L) {
    __shared__ __align__(16) float r_s[1024];
    __shared__ float acc_s[16][128];
    __shared__ float dot_s[128];
    __shared__ float s_sh;

    int tid  = threadIdx.x;
    int lane = tid & 31;
    int w    = tid >> 5;

    PROLOGUE()

    int colbase = blockIdx.x * 128;
    size_t c4   = (size_t)(colbase >> 2) + lane;   // u64 = 4 halves
    int rowg    = blockIdx.y * 1024 + w * 64;
    int il      = w * 64;

    const unsigned long long* Au = (const unsigned long long*)g_Ah;
    float a0 = 0.f, a1 = 0.f, a2 = 0.f, a3 = 0.f;

    #pragma unroll 4
    for (int ii = 0; ii < 64; ii++) {
        float rv = r_s[il + ii];
        unsigned long long av = Au[(size_t)(rowg + ii) * (Nn / 4) + c4];
        unsigned int lo = (unsigned int)av;
        unsigned int hi = (unsigned int)(av >> 32);
        float2 f0 = __half22float2(*(__half2*)&lo);
        float2 f1 = __half22float2(*(__half2*)&hi);
        a0 += rv * f0.x; a1 += rv * f0.y;
        a2 += rv * f1.x; a3 += rv * f1.y;
    }
    acc_s[w][lane * 4]     = a0;
    acc_s[w][lane * 4 + 1] = a1;
    acc_s[w][lane * 4 + 2] = a2;
    acc_s[w][lane * 4 + 3] = a3;
    __syncthreads();

    EPILOGUE(128, t)
}

// ---------------------------------------------------------------------------
// fp8 step: grid (32 col-tiles of 128, 4 row-quarters), block 512.
// Lane covers 8 cols (u64 = 8 e4m3); half-warps handle row parity.
__global__ void __launch_bounds__(512) step8_kernel(int k, int cnt,
                                                    const float* __restrict__ C,
                                                    const float* __restrict__ L) {
    __shared__ __align__(16) float r_s[1024];
    __shared__ float acc_s[16][128];
    __shared__ float dot_s[128];
    __shared__ float s_sh;

    int tid  = threadIdx.x;
    int lane = tid & 31;
    int w    = tid >> 5;

    PROLOGUE()

    int colbase = blockIdx.x * 128;
    int rowg    = blockIdx.y * 1024 + w * 64;
    int il      = w * 64;
    int half    = lane >> 4;                       // 0/1: row parity
    int lpos    = lane & 15;                       // col-group within tile
    size_t cu   = (size_t)(colbase >> 3) + lpos;   // u64 index within a row

    const unsigned long long* Au = g_A8;           // row = Nn/8 = 512 u64
    float acc[8];
    #pragma unroll
    for (int c = 0; c < 8; c++) acc[c] = 0.f;

    #pragma unroll 4
    for (int ii = 0; ii < 64; ii += 2) {
        float rv = r_s[il + ii + half];
        unsigned long long av = Au[(size_t)(rowg + ii + half) * (Nn / 8) + cu];
        unsigned short p0 = (unsigned short)av;
        unsigned short p1 = (unsigned short)(av >> 16);
        unsigned short p2 = (unsigned short)(av >> 32);
        unsigned short p3 = (unsigned short)(av >> 48);
        unsigned int h01, h23, h45, h67;
        asm("cvt.rn.f16x2.e4m3x2 %0, %1;" : "=r"(h01) : "h"(p0));
        asm("cvt.rn.f16x2.e4m3x2 %0, %1;" : "=r"(h23) : "h"(p1));
        asm("cvt.rn.f16x2.e4m3x2 %0, %1;" : "=r"(h45) : "h"(p2));
        asm("cvt.rn.f16x2.e4m3x2 %0, %1;" : "=r"(h67) : "h"(p3));
        float2 f0 = __half22float2(*(__half2*)&h01);
        float2 f1 = __half22float2(*(__half2*)&h23);
        float2 f2 = __half22float2(*(__half2*)&h45);
        float2 f3 = __half22float2(*(__half2*)&h67);
        acc[0] += rv * f0.x; acc[1] += rv * f0.y;
        acc[2] += rv * f1.x; acc[3] += rv * f1.y;
        acc[4] += rv * f2.x; acc[5] += rv * f2.y;
        acc[6] += rv * f3.x; acc[7] += rv * f3.y;
    }

    // fold the two row-parity half-warps (lanes 0..15 keep the sum)
    #pragma unroll
    for (int c = 0; c < 8; c++)
        acc[c] += __shfl_down_sync(0xffffffffu, acc[c], 16);
    if (lane < 16) {
        #pragma unroll
        for (int c = 0; c < 8; c++)
            acc_s[w][lpos * 8 + c] = acc[c];
    }
    __syncthreads();

    EPILOGUE(128, t * FP8_SCALE_INV)
}

// ---------------------------------------------------------------------------
// phi: p_k = r_k B - s_k D, q_k = s_k = r_k.L, a_k = r_k.1
__global__ void __launch_bounds__(256) phi_kernel(const float* __restrict__ B,
                                                  const float* __restrict__ D,
                                                  const float* __restrict__ L) {
    __shared__ float r_s[Nn];
    __shared__ float red[256];
    __shared__ float sres[10];
    int k = blockIdx.x;
    int tid = threadIdx.x;

    for (int i = tid; i < Nn; i += 256)
        r_s[i] = g_R[k][0][i] + g_R[k][1][i] + g_R[k][2][i] + g_R[k][3][i];
    __syncthreads();

    float acc[10];
    #pragma unroll
    for (int c = 0; c < 10; c++) acc[c] = 0.f;

    for (int i = tid; i < Nn; i += 256) {
        float rv = r_s[i];
        float4 b0 = *(const float4*)(B + i * INW);
        float4 b1 = *(const float4*)(B + i * INW + 4);
        acc[0] += rv * b0.x; acc[1] += rv * b0.y;
        acc[2] += rv * b0.z; acc[3] += rv * b0.w;
        acc[4] += rv * b1.x; acc[5] += rv * b1.y;
        acc[6] += rv * b1.z; acc[7] += rv * b1.w;
        acc[8] += rv * L[i];
        acc[9] += rv;                 // h0 = ones
    }

    #pragma unroll
    for (int c = 0; c < 10; c++) {
        red[tid] = acc[c];
        __syncthreads();
        for (int off = 128; off > 0; off >>= 1) {
            if (tid < off) red[tid] += red[tid + off];
            __syncthreads();
        }
        if (tid == 0) sres[c] = red[0];
        __syncthreads();
    }

    if (tid == 0) {
        float s = sres[8];
        #pragma unroll
        for (int c = 0; c < INW; c++) g_PQ[k][c] = sres[c] - s * D[c];
        g_PQ[k][8] = s;
        g_PQ[k][9] = sres[9];
    }
}

// ---------------------------------------------------------------------------
// conv: y_t = a_t + D.u_t + sum_{k<min(t,K)} [ p_k.u_{t-1-k} + q_k yobs_{t-1-k} ]
__global__ void __launch_bounds__(256) conv_kernel(const float* __restrict__ u,
                                                   const float* __restrict__ yobs,
                                                   const float* __restrict__ D,
                                                   float* __restrict__ out) {
    __shared__ float pq[K_TR][10];
    __shared__ float us[512][9];      // [local sidx][0..7]=u, [8]=yobs
    int tid = threadIdx.x;
    int t0  = blockIdx.x * 256;

    for (int idx = tid; idx < K_TR * 10; idx += 256)
        pq[idx / 10][idx % 10] = g_PQ[idx / 10][idx % 10];

    for (int l = tid; l < 512; l += 256) {
        int sidx = t0 - 256 + l;
        if (sidx >= 0 && sidx < Tt) {
            #pragma unroll
            for (int c = 0; c < INW; c++) us[l][c] = u[c * Tt + sidx];
            us[l][8] = yobs[sidx];
        } else {
            #pragma unroll
            for (int c = 0; c < 9; c++) us[l][c] = 0.f;
        }
    }
    __syncthreads();

    int t = t0 + tid;
    float y = 0.f;
    #pragma unroll
    for (int c = 0; c < INW; c++) y += D[c] * u[c * Tt + t];
    if (t < K_TR) y += pq[t][9];      // a_t = r_t . h0 (decayed ~0 beyond K)

    int kmax = min(t, K_TR);
    for (int kk = 0; kk < kmax; kk++) {
        int l = tid + 255 - kk;       // (t-1-kk) - (t0-256)
        float a = pq[kk][8] * us[l][8];
        #pragma unroll
        for (int c = 0; c < INW; c++) a += pq[kk][c] * us[l][c];
        y += a;
    }
    out[t] = 3.f * tanhf(y);
}

// ---------------------------------------------------------------------------
extern "C" void kernel_launch(void* const* d_in, const int* in_sizes, int n_in,
                              void* d_out, int out_size) {
    const float* u    = (const float*)d_in[0];  // [8,4096]
    const float* yobs = (const float*)d_in[1];  // [1,4096]
    const float* A    = (const float*)d_in[2];  // [4096,4096]
    const float* B    = (const float*)d_in[3];  // [4096,8]
    const float* C    = (const float*)d_in[4];  // [1,4096]
    const float* D    = (const float*)d_in[5];  // [1,8]
    const float* L    = (const float*)d_in[6];  // [4096,1]
    float* out = (float*)d_out;                 // [1,4096]
    (void)in_sizes; (void)n_in; (void)out_size;

    convert_kernel<<<(Nn * Nn / 4) / 256, 256>>>((const float4*)A);
    init_kernel<<<Nn / 256, 256>>>(C, L);
    step16r_kernel<<<dim3(32, QP), 512>>>(0, 1, C, L);
    for (int k = 1; k < K_F16R; k++)
        step16r_kernel<<<dim3(32, QP), 512>>>(k, 128, C, L);
    for (int k = K_F16R; k < FP8_START; k++)
        step16_kernel<<<dim3(32, QP), 512>>>(k, 128, C, L);
    for (int k = FP8_START; k < K_TR - 1; k++)
        step8_kernel<<<dim3(32, QP), 512>>>(k, 128, C, L);
    phi_kernel<<<K_TR, 256>>>(B, D, L);
    conv_kernel<<<Tt / 256, 256>>>(u, yobs, D, out);
}

// round 15
// speedup vs baseline: 1.9885x; 1.0560x over previous
#include <cuda_runtime.h>
#include <cuda_fp16.h>
#include <cuda_fp8.h>
#include <math.h>

// StateNeuronSep: Luenberger observer, ORDER=4096, SEQ=4096, IN=8, OUT=1.
//
// y_t = r_t.h0 + sum_{k<t} [ (r_k B').u_{t-1-k} + (r_k L) yobs_{t-1-k} ] + D.u_t
// r_{k+1} = r_k A - (r_k.L) C   (row Krylov, rank-1 fold; M never materialized)
// Ladder: k in [0,8)  fp16 + fp8-residual (~fp23) | [8,48) fp16 | [48,72) fp8.
// All A loads are 128-bit (uint4) — doubles per-SM bytes-in-flight to clear
// the L2 latency knee (Little's law: ~12KB/SM needed at 250cy, 49 B/cyc/SM).

#define Nn 4096
#define Tt 4096
#define INW 8
#define K_TR 72
#define K_F16R 8
#define FP8_START 48
#define QP 4
#define FP8_SCALE_INV 6.103515625e-05f    // 2^-14
#define RES_SCALE     16777216.f          // 2^24
#define RES_SCALE_INV 5.9604644775390625e-08f  // 2^-24

// Scratch (device globals; no allocation allowed)
__device__ float   g_R[K_TR][QP][Nn];            // partial planes
__device__ float   g_S[K_TR][256];               // per-CTA partial s = r.L
__device__ float   g_PQ[K_TR][12];               // p[0..7], [8]=s_k, [9]=r_k.1
__device__ __half2 g_Ah[(Nn * Nn) / 2];          // 32 MB fp16 A
__device__ unsigned long long g_A8[(Nn * Nn) / 8];  // 16 MB fp8 (e4m3, x2^14) A
__device__ unsigned long long g_E8[(Nn * Nn) / 8];  // 16 MB fp8 residual (x2^24)

// ---------------------------------------------------------------------------
// one-time A (fp32, streamed) -> fp16 + fp8 + fp8-residual.  4M float4 elems.
__global__ void __launch_bounds__(256) convert_kernel(const float4* __restrict__ A4) {
    int idx = blockIdx.x * 256 + threadIdx.x;      // 0 .. 4M-1
    float4 v = __ldcs(A4 + idx);
    __half2 h0 = __floats2half2_rn(v.x, v.y);
    __half2 h1 = __floats2half2_rn(v.z, v.w);
    uint2 packed;
    packed.x = *reinterpret_cast<unsigned int*>(&h0);
    packed.y = *reinterpret_cast<unsigned int*>(&h1);
    ((uint2*)g_Ah)[idx] = packed;
    const float sc = 16384.f;                      // max |A|*2^14 ~ 399 < 448
    unsigned int b0 = __nv_cvt_float_to_fp8(v.x * sc, __NV_SATFINITE, __NV_E4M3);
    unsigned int b1 = __nv_cvt_float_to_fp8(v.y * sc, __NV_SATFINITE, __NV_E4M3);
    unsigned int b2 = __nv_cvt_float_to_fp8(v.z * sc, __NV_SATFINITE, __NV_E4M3);
    unsigned int b3 = __nv_cvt_float_to_fp8(v.w * sc, __NV_SATFINITE, __NV_E4M3);
    ((unsigned int*)g_A8)[idx] = b0 | (b1 << 8) | (b2 << 16) | (b3 << 24);
    float2 f0 = __half22float2(h0);
    float2 f1 = __half22float2(h1);
    unsigned int e0 = __nv_cvt_float_to_fp8((v.x - f0.x) * RES_SCALE, __NV_SATFINITE, __NV_E4M3);
    unsigned int e1 = __nv_cvt_float_to_fp8((v.y - f0.y) * RES_SCALE, __NV_SATFINITE, __NV_E4M3);
    unsigned int e2 = __nv_cvt_float_to_fp8((v.z - f1.x) * RES_SCALE, __NV_SATFINITE, __NV_E4M3);
    unsigned int e3 = __nv_cvt_float_to_fp8((v.w - f1.y) * RES_SCALE, __NV_SATFINITE, __NV_E4M3);
    ((unsigned int*)g_E8)[idx] = e0 | (e1 << 8) | (e2 << 16) | (e3 << 24);
}

// ---------------------------------------------------------------------------
// init: r_0 = C in plane 0, zeros elsewhere; block 0 computes s_0 = C.L.
__global__ void init_kernel(const float* __restrict__ C,
                            const float* __restrict__ L) {
    __shared__ float red[256];
    int tid = threadIdx.x;
    int j = blockIdx.x * 256 + tid;
    if (j < Nn) {
        g_R[0][0][j] = C[j];
        g_R[0][1][j] = 0.f;
        g_R[0][2][j] = 0.f;
        g_R[0][3][j] = 0.f;
    }
    if (blockIdx.x == 0) {
        float sp = 0.f;
        for (int i = tid; i < Nn; i += 256) sp += C[i] * L[i];
        red[tid] = sp;
        __syncthreads();
        for (int off = 128; off > 0; off >>= 1) {
            if (tid < off) red[tid] += red[tid + off];
            __syncthreads();
        }
        if (tid == 0) g_S[0][0] = red[0];
    }
}

// ---------------------------------------------------------------------------
#define PROLOGUE()                                                             \
    {                                                                          \
        if (tid < 256) {                                                       \
            const float4* p0 = (const float4*)&g_R[k][0][blockIdx.y * 1024];   \
            const float4* p1 = (const float4*)&g_R[k][1][blockIdx.y * 1024];   \
            const float4* p2 = (const float4*)&g_R[k][2][blockIdx.y * 1024];   \
            const float4* p3 = (const float4*)&g_R[k][3][blockIdx.y * 1024];   \
            float4 a = p0[tid], b = p1[tid], c = p2[tid], d = p3[tid];         \
            ((float4*)r_s)[tid] =                                              \
                make_float4(a.x + b.x + c.x + d.x, a.y + b.y + c.y + d.y,      \
                            a.z + b.z + c.z + d.z, a.w + b.w + c.w + d.w);     \
        } else if (tid >= 480) {                                               \
            int l2 = tid - 480;   /* one warp sums the s partials */           \
            float sp = 0.f;                                                    \
            for (int idx = l2; idx < cnt; idx += 32) sp += g_S[k][idx];        \
            _Pragma("unroll")                                                  \
            for (int off = 16; off > 0; off >>= 1)                             \
                sp += __shfl_xor_sync(0xffffffffu, sp, off);                   \
            if (l2 == 0) s_sh = sp;                                            \
        }                                                                      \
    }                                                                          \
    __syncthreads();

#define EPILOGUE(WIDTH, SCALE_EXPR)                                            \
    if (tid < (WIDTH)) {                                                       \
        float t = 0.f;                                                         \
        _Pragma("unroll")                                                      \
        for (int q = 0; q < 16; q++) t += acc_s[q][tid];                       \
        t = (SCALE_EXPR);                                                      \
        int j = colbase + tid;                                                 \
        if (blockIdx.y == 0) t -= s_sh * C[j];                                 \
        g_R[k + 1][blockIdx.y][j] = t;                                         \
        dot_s[tid] = t * L[j];                                                 \
    }                                                                          \
    __syncthreads();                                                           \
    for (int off = (WIDTH) / 2; off > 0; off >>= 1) {                          \
        if (tid < off) dot_s[tid] += dot_s[tid + off];                         \
        __syncthreads();                                                       \
    }                                                                          \
    if (tid == 0)                                                              \
        g_S[k + 1][blockIdx.y * gridDim.x + blockIdx.x] = dot_s[0];

// helper: unpack 4 halves (u64) to 4 floats
__device__ __forceinline__ void h4_to_f(unsigned long long v, float* f) {
    unsigned int lo = (unsigned int)v, hi = (unsigned int)(v >> 32);
    float2 a = __half22float2(*(__half2*)&lo);
    float2 b = __half22float2(*(__half2*)&hi);
    f[0] = a.x; f[1] = a.y; f[2] = b.x; f[3] = b.y;
}
// helper: unpack 8 e4m3 (u64) to 8 floats
__device__ __forceinline__ void e8_to_f(unsigned long long v, float* f) {
    unsigned short p0 = (unsigned short)v;
    unsigned short p1 = (unsigned short)(v >> 16);
    unsigned short p2 = (unsigned short)(v >> 32);
    unsigned short p3 = (unsigned short)(v >> 48);
    unsigned int h01, h23, h45, h67;
    asm("cvt.rn.f16x2.e4m3x2 %0, %1;" : "=r"(h01) : "h"(p0));
    asm("cvt.rn.f16x2.e4m3x2 %0, %1;" : "=r"(h23) : "h"(p1));
    asm("cvt.rn.f16x2.e4m3x2 %0, %1;" : "=r"(h45) : "h"(p2));
    asm("cvt.rn.f16x2.e4m3x2 %0, %1;" : "=r"(h67) : "h"(p3));
    float2 a = __half22float2(*(__half2*)&h01);
    float2 b = __half22float2(*(__half2*)&h23);
    float2 c = __half22float2(*(__half2*)&h45);
    float2 d = __half22float2(*(__half2*)&h67);
    f[0] = a.x; f[1] = a.y; f[2] = b.x; f[3] = b.y;
    f[4] = c.x; f[5] = c.y; f[6] = d.x; f[7] = d.y;
}

// ---------------------------------------------------------------------------
// fp16 + fp8-residual step (~fp23): grid (32,4), block 512.
// Lane covers 8 cols (uint4 fp16 + u64 residual); half-warps on row parity.
__global__ void __launch_bounds__(512) step16r_kernel(int k, int cnt,
                                                      const float* __restrict__ C,
                                                      const float* __restrict__ L) {
    __shared__ __align__(16) float r_s[1024];
    __shared__ float acc_s[16][128];
    __shared__ float dot_s[128];
    __shared__ float s_sh;

    int tid  = threadIdx.x;
    int lane = tid & 31;
    int w    = tid >> 5;

    PROLOGUE()

    int colbase = blockIdx.x * 128;
    int rowg    = blockIdx.y * 1024 + w * 64;
    int il      = w * 64;
    int half    = lane >> 4;                         // 0/1: row parity
    int lpos    = lane & 15;                         // col-group (8 cols)
    size_t c16q = (size_t)(colbase >> 3) + lpos;     // uint4 idx (8 halves), row=512
    size_t cuE  = (size_t)(colbase >> 3) + lpos;     // residual u64, row=512

    const uint4* A16q = (const uint4*)g_Ah;
    const unsigned long long* E8u = g_E8;

    float acc[8];
    #pragma unroll
    for (int c = 0; c < 8; c++) acc[c] = 0.f;

    #pragma unroll 8
    for (int ii = 0; ii < 64; ii += 2) {
        int gr = rowg + ii + half;
        float rv = r_s[il + ii + half];
        uint4 av = A16q[(size_t)gr * (Nn / 8) + c16q];
        unsigned long long ev = E8u[(size_t)gr * (Nn / 8) + cuE];
        float f[8], e[8];
        h4_to_f(((unsigned long long)av.y << 32) | av.x, f);
        h4_to_f(((unsigned long long)av.w << 32) | av.z, f + 4);
        e8_to_f(ev, e);
        #pragma unroll
        for (int c = 0; c < 8; c++)
            acc[c] += rv * fmaf(e[c], RES_SCALE_INV, f[c]);
    }

    #pragma unroll
    for (int c = 0; c < 8; c++)
        acc[c] += __shfl_down_sync(0xffffffffu, acc[c], 16);
    if (lane < 16) {
        #pragma unroll
        for (int c = 0; c < 8; c++)
            acc_s[w][lpos * 8 + c] = acc[c];
    }
    __syncthreads();

    EPILOGUE(128, t)
}

// ---------------------------------------------------------------------------
// fp16 step: grid (32,4), block 512. Lane covers 8 cols (uint4 = 8 halves);
// half-warps on row parity.
__global__ void __launch_bounds__(512) step16_kernel(int k, int cnt,
                                                     const float* __restrict__ C,
                                                     const float* __restrict__ L) {
    __shared__ __align__(16) float r_s[1024];
    __shared__ float acc_s[16][128];
    __shared__ float dot_s[128];
    __shared__ float s_sh;

    int tid  = threadIdx.x;
    int lane = tid & 31;
    int w    = tid >> 5;

    PROLOGUE()

    int colbase = blockIdx.x * 128;
    int rowg    = blockIdx.y * 1024 + w * 64;
    int il      = w * 64;
    int half    = lane >> 4;
    int lpos    = lane & 15;
    size_t c16q = (size_t)(colbase >> 3) + lpos;   // uint4 idx, row = 512

    const uint4* A16q = (const uint4*)g_Ah;

    float acc[8];
    #pragma unroll
    for (int c = 0; c < 8; c++) acc[c] = 0.f;

    #pragma unroll 8
    for (int ii = 0; ii < 64; ii += 2) {
        int gr = rowg + ii + half;
        float rv = r_s[il + ii + half];
        uint4 av = A16q[(size_t)gr * (Nn / 8) + c16q];
        float f[8];
        h4_to_f(((unsigned long long)av.y << 32) | av.x, f);
        h4_to_f(((unsigned long long)av.w << 32) | av.z, f + 4);
        #pragma unroll
        for (int c = 0; c < 8; c++) acc[c] += rv * f[c];
    }

    #pragma unroll
    for (int c = 0; c < 8; c++)
        acc[c] += __shfl_down_sync(0xffffffffu, acc[c], 16);
    if (lane < 16) {
        #pragma unroll
        for (int c = 0; c < 8; c++)
            acc_s[w][lpos * 8 + c] = acc[c];
    }
    __syncthreads();

    EPILOGUE(128, t)
}

// ---------------------------------------------------------------------------
// fp8 step: grid (32,4), block 512. Lane covers 16 cols (uint4 = 16 e4m3);
// quarter-warps on row parity (4 rows per iteration).
__global__ void __launch_bounds__(512) step8_kernel(int k, int cnt,
                                                    const float* __restrict__ C,
                                                    const float* __restrict__ L) {
    __shared__ __align__(16) float r_s[1024];
    __shared__ float acc_s[16][128];
    __shared__ float dot_s[128];
    __shared__ float s_sh;

    int tid  = threadIdx.x;
    int lane = tid & 31;
    int w    = tid >> 5;

    PROLOGUE()

    int colbase = blockIdx.x * 128;
    int rowg    = blockIdx.y * 1024 + w * 64;
    int il      = w * 64;
    int quarter = lane >> 3;                        // 0..3: row parity
    int lpos    = lane & 7;                         // col-group (16 cols)
    size_t cq   = (size_t)(colbase >> 4) + lpos;    // uint4 idx (16 fp8), row=256

    const uint4* A8q = (const uint4*)g_A8;

    float acc[16];
    #pragma unroll
    for (int c = 0; c < 16; c++) acc[c] = 0.f;

    #pragma unroll 4
    for (int ii = 0; ii < 64; ii += 4) {
        int gr = rowg + ii + quarter;
        float rv = r_s[il + ii + quarter];
        uint4 av = A8q[(size_t)gr * (Nn / 16) + cq];
        float f[16];
        e8_to_f(((unsigned long long)av.y << 32) | av.x, f);
        e8_to_f(((unsigned long long)av.w << 32) | av.z, f + 8);
        #pragma unroll
        for (int c = 0; c < 16; c++) acc[c] += rv * f[c];
    }

    // fold 4 row-parity quarters: q0+q1 / q2+q3 then combine
    #pragma unroll
    for (int c = 0; c < 16; c++) {
        acc[c] += __shfl_down_sync(0xffffffffu, acc[c], 8);
        acc[c] += __shfl_down_sync(0xffffffffu, acc[c], 16);
    }
    if (lane < 8) {
        #pragma unroll
        for (int c = 0; c < 16; c++)
            acc_s[w][lpos * 16 + c] = acc[c];
    }
    __syncthreads();

    EPILOGUE(128, t * FP8_SCALE_INV)
}

// ---------------------------------------------------------------------------
// phi: p_k = r_k B - s_k D, q_k = s_k = r_k.L, a_k = r_k.1
__global__ void __launch_bounds__(256) phi_kernel(const float* __restrict__ B,
                                                  const float* __restrict__ D,
                                                  const float* __restrict__ L) {
    __shared__ float r_s[Nn];
    __shared__ float red[256];
    __shared__ float sres[10];
    int k = blockIdx.x;
    int tid = threadIdx.x;

    for (int i = tid; i < Nn; i += 256)
        r_s[i] = g_R[k][0][i] + g_R[k][1][i] + g_R[k][2][i] + g_R[k][3][i];
    __syncthreads();

    float acc[10];
    #pragma unroll
    for (int c = 0; c < 10; c++) acc[c] = 0.f;

    for (int i = tid; i < Nn; i += 256) {
        float rv = r_s[i];
        float4 b0 = *(const float4*)(B + i * INW);
        float4 b1 = *(const float4*)(B + i * INW + 4);
        acc[0] += rv * b0.x; acc[1] += rv * b0.y;
        acc[2] += rv * b0.z; acc[3] += rv * b0.w;
        acc[4] += rv * b1.x; acc[5] += rv * b1.y;
        acc[6] += rv * b1.z; acc[7] += rv * b1.w;
        acc[8] += rv * L[i];
        acc[9] += rv;                 // h0 = ones
    }

    #pragma unroll
    for (int c = 0; c < 10; c++) {
        red[tid] = acc[c];
        __syncthreads();
        for (int off = 128; off > 0; off >>= 1) {
            if (tid < off) red[tid] += red[tid + off];
            __syncthreads();
        }
        if (tid == 0) sres[c] = red[0];
        __syncthreads();
    }

    if (tid == 0) {
        float s = sres[8];
        #pragma unroll
        for (int c = 0; c < INW; c++) g_PQ[k][c] = sres[c] - s * D[c];
        g_PQ[k][8] = s;
        g_PQ[k][9] = sres[9];
    }
}

// ---------------------------------------------------------------------------
// conv: y_t = a_t + D.u_t + sum_{k<min(t,K)} [ p_k.u_{t-1-k} + q_k yobs_{t-1-k} ]
__global__ void __launch_bounds__(256) conv_kernel(const float* __restrict__ u,
                                                   const float* __restrict__ yobs,
                                                   const float* __restrict__ D,
                                                   float* __restrict__ out) {
    __shared__ float pq[K_TR][10];
    __shared__ float us[512][9];      // [local sidx][0..7]=u, [8]=yobs
    int tid = threadIdx.x;
    int t0  = blockIdx.x * 256;

    for (int idx = tid; idx < K_TR * 10; idx += 256)
        pq[idx / 10][idx % 10] = g_PQ[idx / 10][idx % 10];

    for (int l = tid; l < 512; l += 256) {
        int sidx = t0 - 256 + l;
        if (sidx >= 0 && sidx < Tt) {
            #pragma unroll
            for (int c = 0; c < INW; c++) us[l][c] = u[c * Tt + sidx];
            us[l][8] = yobs[sidx];
        } else {
            #pragma unroll
            for (int c = 0; c < 9; c++) us[l][c] = 0.f;
        }
    }
    __syncthreads();

    int t = t0 + tid;
    float y = 0.f;
    #pragma unroll
    for (int c = 0; c < INW; c++) y += D[c] * u[c * Tt + t];
    if (t < K_TR) y += pq[t][9];      // a_t = r_t . h0 (decayed ~0 beyond K)

    int kmax = min(t, K_TR);
    for (int kk = 0; kk < kmax; kk++) {
        int l = tid + 255 - kk;       // (t-1-kk) - (t0-256)
        float a = pq[kk][8] * us[l][8];
        #pragma unroll
        for (int c = 0; c < INW; c++) a += pq[kk][c] * us[l][c];
        y += a;
    }
    out[t] = 3.f * tanhf(y);
}

// ---------------------------------------------------------------------------
extern "C" void kernel_launch(void* const* d_in, const int* in_sizes, int n_in,
                              void* d_out, int out_size) {
    const float* u    = (const float*)d_in[0];  // [8,4096]
    const float* yobs = (const float*)d_in[1];  // [1,4096]
    const float* A    = (const float*)d_in[2];  // [4096,4096]
    const float* B    = (const float*)d_in[3];  // [4096,8]
    const float* C    = (const float*)d_in[4];  // [1,4096]
    const float* D    = (const float*)d_in[5];  // [1,8]
    const float* L    = (const float*)d_in[6];  // [4096,1]
    float* out = (float*)d_out;                 // [1,4096]
    (void)in_sizes; (void)n_in; (void)out_size;

    convert_kernel<<<(Nn * Nn / 4) / 256, 256>>>((const float4*)A);
    init_kernel<<<Nn / 256, 256>>>(C, L);
    step16r_kernel<<<dim3(32, QP), 512>>>(0, 1, C, L);
    for (int k = 1; k < K_F16R; k++)
        step16r_kernel<<<dim3(32, QP), 512>>>(k, 128, C, L);
    for (int k = K_F16R; k < FP8_START; k++)
        step16_kernel<<<dim3(32, QP), 512>>>(k, 128, C, L);
    for (int k = FP8_START; k < K_TR - 1; k++)
        step8_kernel<<<dim3(32, QP), 512>>>(k, 128, C, L);
    phi_kernel<<<K_TR, 256>>>(B, D, L);
    conv_kernel<<<Tt / 256, 256>>>(u, yobs, D, out);
}

// round 16
// speedup vs baseline: 2.0340x; 1.0228x over previous
#include <cuda_runtime.h>
#include <cuda_fp16.h>
#include <cuda_fp8.h>
#include <math.h>

// StateNeuronSep: Luenberger observer, ORDER=4096, SEQ=4096, IN=8, OUT=1.
//
// y_t = r_t.h0 + sum_{k<t} [ (r_k B').u_{t-1-k} + (r_k L) yobs_{t-1-k} ] + D.u_t
// r_{k+1} = r_k A - (r_k.L) C   (row Krylov, rank-1 fold; M never materialized)
// Ladder: k in [0,8)  fp16 + fp8-residual (~fp23) | [8,48) fp16 | [48,72) fp8.
// Steps use grid (64 col-tiles of 64, 4 row-quarters) = 256 CTAs (~2/SM, no
// idle SMs) with 128-bit A loads — max aggregate bytes in flight at L2.

#define Nn 4096
#define Tt 4096
#define INW 8
#define K_TR 72
#define K_F16R 8
#define FP8_START 48
#define QP 4
#define FP8_SCALE_INV 6.103515625e-05f    // 2^-14
#define RES_SCALE     16777216.f          // 2^24
#define RES_SCALE_INV 5.9604644775390625e-08f  // 2^-24

// Scratch (device globals; no allocation allowed)
__device__ float   g_R[K_TR][QP][Nn];            // partial planes
__device__ float   g_S[K_TR][256];               // per-CTA partial s = r.L
__device__ float   g_PQ[K_TR][12];               // p[0..7], [8]=s_k, [9]=r_k.1
__device__ __half2 g_Ah[(Nn * Nn) / 2];          // 32 MB fp16 A
__device__ unsigned long long g_A8[(Nn * Nn) / 8];  // 16 MB fp8 (e4m3, x2^14) A
__device__ unsigned long long g_E8[(Nn * Nn) / 8];  // 16 MB fp8 residual (x2^24)

// ---------------------------------------------------------------------------
// one-time A (fp32, streamed) -> fp16 + fp8 + fp8-residual.  4M float4 elems.
__global__ void __launch_bounds__(256) convert_kernel(const float4* __restrict__ A4) {
    int idx = blockIdx.x * 256 + threadIdx.x;      // 0 .. 4M-1
    float4 v = __ldcs(A4 + idx);
    __half2 h0 = __floats2half2_rn(v.x, v.y);
    __half2 h1 = __floats2half2_rn(v.z, v.w);
    uint2 packed;
    packed.x = *reinterpret_cast<unsigned int*>(&h0);
    packed.y = *reinterpret_cast<unsigned int*>(&h1);
    ((uint2*)g_Ah)[idx] = packed;
    const float sc = 16384.f;                      // max |A|*2^14 ~ 399 < 448
    unsigned int b0 = __nv_cvt_float_to_fp8(v.x * sc, __NV_SATFINITE, __NV_E4M3);
    unsigned int b1 = __nv_cvt_float_to_fp8(v.y * sc, __NV_SATFINITE, __NV_E4M3);
    unsigned int b2 = __nv_cvt_float_to_fp8(v.z * sc, __NV_SATFINITE, __NV_E4M3);
    unsigned int b3 = __nv_cvt_float_to_fp8(v.w * sc, __NV_SATFINITE, __NV_E4M3);
    ((unsigned int*)g_A8)[idx] = b0 | (b1 << 8) | (b2 << 16) | (b3 << 24);
    float2 f0 = __half22float2(h0);
    float2 f1 = __half22float2(h1);
    unsigned int e0 = __nv_cvt_float_to_fp8((v.x - f0.x) * RES_SCALE, __NV_SATFINITE, __NV_E4M3);
    unsigned int e1 = __nv_cvt_float_to_fp8((v.y - f0.y) * RES_SCALE, __NV_SATFINITE, __NV_E4M3);
    unsigned int e2 = __nv_cvt_float_to_fp8((v.z - f1.x) * RES_SCALE, __NV_SATFINITE, __NV_E4M3);
    unsigned int e3 = __nv_cvt_float_to_fp8((v.w - f1.y) * RES_SCALE, __NV_SATFINITE, __NV_E4M3);
    ((unsigned int*)g_E8)[idx] = e0 | (e1 << 8) | (e2 << 16) | (e3 << 24);
}

// ---------------------------------------------------------------------------
// init: r_0 = C in plane 0, zeros elsewhere; block 0 computes s_0 = C.L.
__global__ void init_kernel(const float* __restrict__ C,
                            const float* __restrict__ L) {
    __shared__ float red[256];
    int tid = threadIdx.x;
    int j = blockIdx.x * 256 + tid;
    if (j < Nn) {
        g_R[0][0][j] = C[j];
        g_R[0][1][j] = 0.f;
        g_R[0][2][j] = 0.f;
        g_R[0][3][j] = 0.f;
    }
    if (blockIdx.x == 0) {
        float sp = 0.f;
        for (int i = tid; i < Nn; i += 256) sp += C[i] * L[i];
        red[tid] = sp;
        __syncthreads();
        for (int off = 128; off > 0; off >>= 1) {
            if (tid < off) red[tid] += red[tid + off];
            __syncthreads();
        }
        if (tid == 0) g_S[0][0] = red[0];
    }
}

// ---------------------------------------------------------------------------
#define PROLOGUE()                                                             \
    {                                                                          \
        if (tid < 256) {                                                       \
            const float4* p0 = (const float4*)&g_R[k][0][blockIdx.y * 1024];   \
            const float4* p1 = (const float4*)&g_R[k][1][blockIdx.y * 1024];   \
            const float4* p2 = (const float4*)&g_R[k][2][blockIdx.y * 1024];   \
            const float4* p3 = (const float4*)&g_R[k][3][blockIdx.y * 1024];   \
            float4 a = p0[tid], b = p1[tid], c = p2[tid], d = p3[tid];         \
            ((float4*)r_s)[tid] =                                              \
                make_float4(a.x + b.x + c.x + d.x, a.y + b.y + c.y + d.y,      \
                            a.z + b.z + c.z + d.z, a.w + b.w + c.w + d.w);     \
        } else if (tid >= 480) {                                               \
            int l2 = tid - 480;   /* one warp sums the s partials */           \
            float sp = 0.f;                                                    \
            for (int idx = l2; idx < cnt; idx += 32) sp += g_S[k][idx];        \
            _Pragma("unroll")                                                  \
            for (int off = 16; off > 0; off >>= 1)                             \
                sp += __shfl_xor_sync(0xffffffffu, sp, off);                   \
            if (l2 == 0) s_sh = sp;                                            \
        }                                                                      \
    }                                                                          \
    __syncthreads();

#define EPILOGUE(WIDTH, SCALE_EXPR)                                            \
    if (tid < (WIDTH)) {                                                       \
        float t = 0.f;                                                         \
        _Pragma("unroll")                                                      \
        for (int q = 0; q < 16; q++) t += acc_s[q][tid];                       \
        t = (SCALE_EXPR);                                                      \
        int j = colbase + tid;                                                 \
        if (blockIdx.y == 0) t -= s_sh * C[j];                                 \
        g_R[k + 1][blockIdx.y][j] = t;                                         \
        dot_s[tid] = t * L[j];                                                 \
    }                                                                          \
    __syncthreads();                                                           \
    for (int off = (WIDTH) / 2; off > 0; off >>= 1) {                          \
        if (tid < off) dot_s[tid] += dot_s[tid + off];                         \
        __syncthreads();                                                       \
    }                                                                          \
    if (tid == 0)                                                              \
        g_S[k + 1][blockIdx.y * gridDim.x + blockIdx.x] = dot_s[0];

// helper: unpack 4 halves (u64) to 4 floats
__device__ __forceinline__ void h4_to_f(unsigned long long v, float* f) {
    unsigned int lo = (unsigned int)v, hi = (unsigned int)(v >> 32);
    float2 a = __half22float2(*(__half2*)&lo);
    float2 b = __half22float2(*(__half2*)&hi);
    f[0] = a.x; f[1] = a.y; f[2] = b.x; f[3] = b.y;
}
// helper: unpack 8 e4m3 (u64) to 8 floats
__device__ __forceinline__ void e8_to_f(unsigned long long v, float* f) {
    unsigned short p0 = (unsigned short)v;
    unsigned short p1 = (unsigned short)(v >> 16);
    unsigned short p2 = (unsigned short)(v >> 32);
    unsigned short p3 = (unsigned short)(v >> 48);
    unsigned int h01, h23, h45, h67;
    asm("cvt.rn.f16x2.e4m3x2 %0, %1;" : "=r"(h01) : "h"(p0));
    asm("cvt.rn.f16x2.e4m3x2 %0, %1;" : "=r"(h23) : "h"(p1));
    asm("cvt.rn.f16x2.e4m3x2 %0, %1;" : "=r"(h45) : "h"(p2));
    asm("cvt.rn.f16x2.e4m3x2 %0, %1;" : "=r"(h67) : "h"(p3));
    float2 a = __half22float2(*(__half2*)&h01);
    float2 b = __half22float2(*(__half2*)&h23);
    float2 c = __half22float2(*(__half2*)&h45);
    float2 d = __half22float2(*(__half2*)&h67);
    f[0] = a.x; f[1] = a.y; f[2] = b.x; f[3] = b.y;
    f[4] = c.x; f[5] = c.y; f[6] = d.x; f[7] = d.y;
}

// ---------------------------------------------------------------------------
// fp16 + fp8-residual step (~fp23): grid (64,4), block 512.
// Quarter-warp row parity (4 rows/iter); lane covers 8 cols (uint4 + u64).
__global__ void __launch_bounds__(512) step16r_kernel(int k, int cnt,
                                                      const float* __restrict__ C,
                                                      const float* __restrict__ L) {
    __shared__ __align__(16) float r_s[1024];
    __shared__ float acc_s[16][64];
    __shared__ float dot_s[64];
    __shared__ float s_sh;

    int tid  = threadIdx.x;
    int lane = tid & 31;
    int w    = tid >> 5;

    PROLOGUE()

    int colbase = blockIdx.x * 64;
    int rowg    = blockIdx.y * 1024 + w * 64;
    int il      = w * 64;
    int quarter = lane >> 3;                         // 0..3: row parity
    int lpos    = lane & 7;                          // col-group (8 cols)
    size_t c16q = (size_t)(colbase >> 3) + lpos;     // uint4 (8 halves), row=512
    size_t cuE  = (size_t)(colbase >> 3) + lpos;     // residual u64, row=512

    const uint4* A16q = (const uint4*)g_Ah;
    const unsigned long long* E8u = g_E8;

    float acc[8];
    #pragma unroll
    for (int c = 0; c < 8; c++) acc[c] = 0.f;

    #pragma unroll 8
    for (int ii = 0; ii < 64; ii += 4) {
        int gr = rowg + ii + quarter;
        float rv = r_s[il + ii + quarter];
        uint4 av = A16q[(size_t)gr * (Nn / 8) + c16q];
        unsigned long long ev = E8u[(size_t)gr * (Nn / 8) + cuE];
        float f[8], e[8];
        h4_to_f(((unsigned long long)av.y << 32) | av.x, f);
        h4_to_f(((unsigned long long)av.w << 32) | av.z, f + 4);
        e8_to_f(ev, e);
        #pragma unroll
        for (int c = 0; c < 8; c++)
            acc[c] += rv * fmaf(e[c], RES_SCALE_INV, f[c]);
    }

    // fold the 4 row-parity quarters (lanes 0..7 keep the sum)
    #pragma unroll
    for (int c = 0; c < 8; c++) {
        acc[c] += __shfl_down_sync(0xffffffffu, acc[c], 8);
        acc[c] += __shfl_down_sync(0xffffffffu, acc[c], 16);
    }
    if (lane < 8) {
        #pragma unroll
        for (int c = 0; c < 8; c++)
            acc_s[w][lpos * 8 + c] = acc[c];
    }
    __syncthreads();

    EPILOGUE(64, t)
}

// ---------------------------------------------------------------------------
// fp16 step: grid (64,4), block 512. Quarter-warp row parity; lane = 8 cols.
__global__ void __launch_bounds__(512) step16_kernel(int k, int cnt,
                                                     const float* __restrict__ C,
                                                     const float* __restrict__ L) {
    __shared__ __align__(16) float r_s[1024];
    __shared__ float acc_s[16][64];
    __shared__ float dot_s[64];
    __shared__ float s_sh;

    int tid  = threadIdx.x;
    int lane = tid & 31;
    int w    = tid >> 5;

    PROLOGUE()

    int colbase = blockIdx.x * 64;
    int rowg    = blockIdx.y * 1024 + w * 64;
    int il      = w * 64;
    int quarter = lane >> 3;
    int lpos    = lane & 7;
    size_t c16q = (size_t)(colbase >> 3) + lpos;   // uint4 idx, row = 512

    const uint4* A16q = (const uint4*)g_Ah;

    float acc[8];
    #pragma unroll
    for (int c = 0; c < 8; c++) acc[c] = 0.f;

    #pragma unroll 8
    for (int ii = 0; ii < 64; ii += 4) {
        int gr = rowg + ii + quarter;
        float rv = r_s[il + ii + quarter];
        uint4 av = A16q[(size_t)gr * (Nn / 8) + c16q];
        float f[8];
        h4_to_f(((unsigned long long)av.y << 32) | av.x, f);
        h4_to_f(((unsigned long long)av.w << 32) | av.z, f + 4);
        #pragma unroll
        for (int c = 0; c < 8; c++) acc[c] += rv * f[c];
    }

    #pragma unroll
    for (int c = 0; c < 8; c++) {
        acc[c] += __shfl_down_sync(0xffffffffu, acc[c], 8);
        acc[c] += __shfl_down_sync(0xffffffffu, acc[c], 16);
    }
    if (lane < 8) {
        #pragma unroll
        for (int c = 0; c < 8; c++)
            acc_s[w][lpos * 8 + c] = acc[c];
    }
    __syncthreads();

    EPILOGUE(64, t)
}

// ---------------------------------------------------------------------------
// fp8 step: grid (64,4), block 512. Eighth-warp row parity (8 rows/iter);
// lane covers 16 cols (uint4 = 16 e4m3).
__global__ void __launch_bounds__(512) step8_kernel(int k, int cnt,
                                                    const float* __restrict__ C,
                                                    const float* __restrict__ L) {
    __shared__ __align__(16) float r_s[1024];
    __shared__ float acc_s[16][64];
    __shared__ float dot_s[64];
    __shared__ float s_sh;

    int tid  = threadIdx.x;
    int lane = tid & 31;
    int w    = tid >> 5;

    PROLOGUE()

    int colbase = blockIdx.x * 64;
    int rowg    = blockIdx.y * 1024 + w * 64;
    int il      = w * 64;
    int eighth  = lane >> 2;                        // 0..7: row parity
    int lpos    = lane & 3;                         // col-group (16 cols)
    size_t cq   = (size_t)(colbase >> 4) + lpos;    // uint4 (16 fp8), row=256

    const uint4* A8q = (const uint4*)g_A8;

    float acc[16];
    #pragma unroll
    for (int c = 0; c < 16; c++) acc[c] = 0.f;

    #pragma unroll 8
    for (int ii = 0; ii < 64; ii += 8) {
        int gr = rowg + ii + eighth;
        float rv = r_s[il + ii + eighth];
        uint4 av = A8q[(size_t)gr * (Nn / 16) + cq];
        float f[16];
        e8_to_f(((unsigned long long)av.y << 32) | av.x, f);
        e8_to_f(((unsigned long long)av.w << 32) | av.z, f + 8);
        #pragma unroll
        for (int c = 0; c < 16; c++) acc[c] += rv * f[c];
    }

    // fold the 8 row-parity groups (lanes 0..3 keep the sum)
    #pragma unroll
    for (int c = 0; c < 16; c++) {
        acc[c] += __shfl_down_sync(0xffffffffu, acc[c], 4);
        acc[c] += __shfl_down_sync(0xffffffffu, acc[c], 8);
        acc[c] += __shfl_down_sync(0xffffffffu, acc[c], 16);
    }
    if (lane < 4) {
        #pragma unroll
        for (int c = 0; c < 16; c++)
            acc_s[w][lpos * 16 + c] = acc[c];
    }
    __syncthreads();

    EPILOGUE(64, t * FP8_SCALE_INV)
}

// ---------------------------------------------------------------------------
// phi: p_k = r_k B - s_k D, q_k = s_k = r_k.L, a_k = r_k.1
__global__ void __launch_bounds__(256) phi_kernel(const float* __restrict__ B,
                                                  const float* __restrict__ D,
                                                  const float* __restrict__ L) {
    __shared__ float r_s[Nn];
    __shared__ float red[256];
    __shared__ float sres[10];
    int k = blockIdx.x;
    int tid = threadIdx.x;

    for (int i = tid; i < Nn; i += 256)
        r_s[i] = g_R[k][0][i] + g_R[k][1][i] + g_R[k][2][i] + g_R[k][3][i];
    __syncthreads();

    float acc[10];
    #pragma unroll
    for (int c = 0; c < 10; c++) acc[c] = 0.f;

    for (int i = tid; i < Nn; i += 256) {
        float rv = r_s[i];
        float4 b0 = *(const float4*)(B + i * INW);
        float4 b1 = *(const float4*)(B + i * INW + 4);
        acc[0] += rv * b0.x; acc[1] += rv * b0.y;
        acc[2] += rv * b0.z; acc[3] += rv * b0.w;
        acc[4] += rv * b1.x; acc[5] += rv * b1.y;
        acc[6] += rv * b1.z; acc[7] += rv * b1.w;
        acc[8] += rv * L[i];
        acc[9] += rv;                 // h0 = ones
    }

    #pragma unroll
    for (int c = 0; c < 10; c++) {
        red[tid] = acc[c];
        __syncthreads();
        for (int off = 128; off > 0; off >>= 1) {
            if (tid < off) red[tid] += red[tid + off];
            __syncthreads();
        }
        if (tid == 0) sres[c] = red[0];
        __syncthreads();
    }

    if (tid == 0) {
        float s = sres[8];
        #pragma unroll
        for (int c = 0; c < INW; c++) g_PQ[k][c] = sres[c] - s * D[c];
        g_PQ[k][8] = s;
        g_PQ[k][9] = sres[9];
    }
}

// ---------------------------------------------------------------------------
// conv: y_t = a_t + D.u_t + sum_{k<min(t,K)} [ p_k.u_{t-1-k} + q_k yobs_{t-1-k} ]
__global__ void __launch_bounds__(256) conv_kernel(const float* __restrict__ u,
                                                   const float* __restrict__ yobs,
                                                   const float* __restrict__ D,
                                                   float* __restrict__ out) {
    __shared__ float pq[K_TR][10];
    __shared__ float us[512][9];      // [local sidx][0..7]=u, [8]=yobs
    int tid = threadIdx.x;
    int t0  = blockIdx.x * 256;

    for (int idx = tid; idx < K_TR * 10; idx += 256)
        pq[idx / 10][idx % 10] = g_PQ[idx / 10][idx % 10];

    for (int l = tid; l < 512; l += 256) {
        int sidx = t0 - 256 + l;
        if (sidx >= 0 && sidx < Tt) {
            #pragma unroll
            for (int c = 0; c < INW; c++) us[l][c] = u[c * Tt + sidx];
            us[l][8] = yobs[sidx];
        } else {
            #pragma unroll
            for (int c = 0; c < 9; c++) us[l][c] = 0.f;
        }
    }
    __syncthreads();

    int t = t0 + tid;
    float y = 0.f;
    #pragma unroll
    for (int c = 0; c < INW; c++) y += D[c] * u[c * Tt + t];
    if (t < K_TR) y += pq[t][9];      // a_t = r_t . h0 (decayed ~0 beyond K)

    int kmax = min(t, K_TR);
    for (int kk = 0; kk < kmax; kk++) {
        int l = tid + 255 - kk;       // (t-1-kk) - (t0-256)
        float a = pq[kk][8] * us[l][8];
        #pragma unroll
        for (int c = 0; c < INW; c++) a += pq[kk][c] * us[l][c];
        y += a;
    }
    out[t] = 3.f * tanhf(y);
}

// ---------------------------------------------------------------------------
extern "C" void kernel_launch(void* const* d_in, const int* in_sizes, int n_in,
                              void* d_out, int out_size) {
    const float* u    = (const float*)d_in[0];  // [8,4096]
    const float* yobs = (const float*)d_in[1];  // [1,4096]
    const float* A    = (const float*)d_in[2];  // [4096,4096]
    const float* B    = (const float*)d_in[3];  // [4096,8]
    const float* C    = (const float*)d_in[4];  // [1,4096]
    const float* D    = (const float*)d_in[5];  // [1,8]
    const float* L    = (const float*)d_in[6];  // [4096,1]
    float* out = (float*)d_out;                 // [1,4096]
    (void)in_sizes; (void)n_in; (void)out_size;

    convert_kernel<<<(Nn * Nn / 4) / 256, 256>>>((const float4*)A);
    init_kernel<<<Nn / 256, 256>>>(C, L);
    step16r_kernel<<<dim3(64, QP), 512>>>(0, 1, C, L);
    for (int k = 1; k < K_F16R; k++)
        step16r_kernel<<<dim3(64, QP), 512>>>(k, 256, C, L);
    for (int k = K_F16R; k < FP8_START; k++)
        step16_kernel<<<dim3(64, QP), 512>>>(k, 256, C, L);
    for (int k = FP8_START; k < K_TR - 1; k++)
        step8_kernel<<<dim3(64, QP), 512>>>(k, 256, C, L);
    phi_kernel<<<K_TR, 256>>>(B, D, L);
    conv_kernel<<<Tt / 256, 256>>>(u, yobs, D, out);
}

// round 17
// speedup vs baseline: 2.2026x; 1.0829x over previous
#include <cuda_runtime.h>
#include <cuda_fp16.h>
#include <cuda_fp8.h>
#include <math.h>

// StateNeuronSep: Luenberger observer, ORDER=4096, SEQ=4096, IN=8, OUT=1.
//
// y_t = r_t.h0 + sum_{k<t} [ (r_k B').u_{t-1-k} + (r_k L) yobs_{t-1-k} ] + D.u_t
// r_{k+1} = r_k A - (r_k.L) C   (row Krylov, rank-1 fold; M never materialized)
// Ladder: k in [0,8) fp16+fp8-residual (~fp23) | [8,44) fp16 | [44,68) fp8.
// Error budget (calibrated): ladder 4.2e-4 (+) trunc X(68)=5.7e-4 => ~7.1e-4.
// Grid (64 col-tiles of 64, 4 row-quarters) = 256 CTAs, 128-bit A loads.

#define Nn 4096
#define Tt 4096
#define INW 8
#define K_TR 68
#define K_F16R 8
#define FP8_START 44
#define QP 4
#define FP8_SCALE_INV 6.103515625e-05f    // 2^-14
#define RES_SCALE     16777216.f          // 2^24
#define RES_SCALE_INV 5.9604644775390625e-08f  // 2^-24

// Scratch (device globals; no allocation allowed)
__device__ float   g_R[K_TR][QP][Nn];            // partial planes
__device__ float   g_S[K_TR][256];               // per-CTA partial s = r.L
__device__ float   g_PQ[K_TR][12];               // p[0..7], [8]=s_k, [9]=r_k.1
__device__ __half2 g_Ah[(Nn * Nn) / 2];          // 32 MB fp16 A
__device__ unsigned long long g_A8[(Nn * Nn) / 8];  // 16 MB fp8 (e4m3, x2^14) A
__device__ unsigned long long g_E8[(Nn * Nn) / 8];  // 16 MB fp8 residual (x2^24)

// ---------------------------------------------------------------------------
// one-time A (fp32, streamed) -> fp16 + fp8 + fp8-residual.  4M float4 elems.
__global__ void __launch_bounds__(256) convert_kernel(const float4* __restrict__ A4) {
    int idx = blockIdx.x * 256 + threadIdx.x;      // 0 .. 4M-1
    float4 v = __ldcs(A4 + idx);
    __half2 h0 = __floats2half2_rn(v.x, v.y);
    __half2 h1 = __floats2half2_rn(v.z, v.w);
    uint2 packed;
    packed.x = *reinterpret_cast<unsigned int*>(&h0);
    packed.y = *reinterpret_cast<unsigned int*>(&h1);
    ((uint2*)g_Ah)[idx] = packed;
    const float sc = 16384.f;                      // max |A|*2^14 ~ 399 < 448
    unsigned int b0 = __nv_cvt_float_to_fp8(v.x * sc, __NV_SATFINITE, __NV_E4M3);
    unsigned int b1 = __nv_cvt_float_to_fp8(v.y * sc, __NV_SATFINITE, __NV_E4M3);
    unsigned int b2 = __nv_cvt_float_to_fp8(v.z * sc, __NV_SATFINITE, __NV_E4M3);
    unsigned int b3 = __nv_cvt_float_to_fp8(v.w * sc, __NV_SATFINITE, __NV_E4M3);
    ((unsigned int*)g_A8)[idx] = b0 | (b1 << 8) | (b2 << 16) | (b3 << 24);
    float2 f0 = __half22float2(h0);
    float2 f1 = __half22float2(h1);
    unsigned int e0 = __nv_cvt_float_to_fp8((v.x - f0.x) * RES_SCALE, __NV_SATFINITE, __NV_E4M3);
    unsigned int e1 = __nv_cvt_float_to_fp8((v.y - f0.y) * RES_SCALE, __NV_SATFINITE, __NV_E4M3);
    unsigned int e2 = __nv_cvt_float_to_fp8((v.z - f1.x) * RES_SCALE, __NV_SATFINITE, __NV_E4M3);
    unsigned int e3 = __nv_cvt_float_to_fp8((v.w - f1.y) * RES_SCALE, __NV_SATFINITE, __NV_E4M3);
    ((unsigned int*)g_E8)[idx] = e0 | (e1 << 8) | (e2 << 16) | (e3 << 24);
}

// ---------------------------------------------------------------------------
// init: r_0 = C in plane 0, zeros elsewhere; block 0 computes s_0 = C.L.
__global__ void init_kernel(const float* __restrict__ C,
                            const float* __restrict__ L) {
    __shared__ float red[256];
    int tid = threadIdx.x;
    int j = blockIdx.x * 256 + tid;
    if (j < Nn) {
        g_R[0][0][j] = C[j];
        g_R[0][1][j] = 0.f;
        g_R[0][2][j] = 0.f;
        g_R[0][3][j] = 0.f;
    }
    if (blockIdx.x == 0) {
        float sp = 0.f;
        for (int i = tid; i < Nn; i += 256) sp += C[i] * L[i];
        red[tid] = sp;
        __syncthreads();
        for (int off = 128; off > 0; off >>= 1) {
            if (tid < off) red[tid] += red[tid + off];
            __syncthreads();
        }
        if (tid == 0) g_S[0][0] = red[0];
    }
}

// ---------------------------------------------------------------------------
#define PROLOGUE()                                                             \
    {                                                                          \
        if (tid < 256) {                                                       \
            const float4* p0 = (const float4*)&g_R[k][0][blockIdx.y * 1024];   \
            const float4* p1 = (const float4*)&g_R[k][1][blockIdx.y * 1024];   \
            const float4* p2 = (const float4*)&g_R[k][2][blockIdx.y * 1024];   \
            const float4* p3 = (const float4*)&g_R[k][3][blockIdx.y * 1024];   \
            float4 a = p0[tid], b = p1[tid], c = p2[tid], d = p3[tid];         \
            ((float4*)r_s)[tid] =                                              \
                make_float4(a.x + b.x + c.x + d.x, a.y + b.y + c.y + d.y,      \
                            a.z + b.z + c.z + d.z, a.w + b.w + c.w + d.w);     \
        } else if (tid >= 480) {                                               \
            int l2 = tid - 480;   /* one warp sums the s partials */           \
            float sp = 0.f;                                                    \
            for (int idx = l2; idx < cnt; idx += 32) sp += g_S[k][idx];        \
            _Pragma("unroll")                                                  \
            for (int off = 16; off > 0; off >>= 1)                             \
                sp += __shfl_xor_sync(0xffffffffu, sp, off);                   \
            if (l2 == 0) s_sh = sp;                                            \
        }                                                                      \
    }                                                                          \
    __syncthreads();

// Epilogue: reduce warp partials per column, fold -s*C on plane 0, write
// plane; per-CTA dot with L via warp shuffles (1 sync, fixed combine order).
#define EPILOGUE(SCALE_EXPR)                                                   \
    if (tid < 64) {                                                            \
        float t = 0.f;                                                         \
        _Pragma("unroll")                                                      \
        for (int q = 0; q < 16; q++) t += acc_s[q][tid];                       \
        t = (SCALE_EXPR);                                                      \
        int j = colbase + tid;                                                 \
        if (blockIdx.y == 0) t -= s_sh * C[j];                                 \
        g_R[k + 1][blockIdx.y][j] = t;                                         \
        float d = t * L[j];                                                    \
        _Pragma("unroll")                                                      \
        for (int off = 16; off > 0; off >>= 1)                                 \
            d += __shfl_xor_sync(0xffffffffu, d, off);                         \
        if (lane == 0) dotp_s[w] = d;                                          \
    }                                                                          \
    __syncthreads();                                                           \
    if (tid == 0)                                                              \
        g_S[k + 1][blockIdx.y * gridDim.x + blockIdx.x] = dotp_s[0] + dotp_s[1];

// helper: unpack 4 halves (u64) to 4 floats
__device__ __forceinline__ void h4_to_f(unsigned long long v, float* f) {
    unsigned int lo = (unsigned int)v, hi = (unsigned int)(v >> 32);
    float2 a = __half22float2(*(__half2*)&lo);
    float2 b = __half22float2(*(__half2*)&hi);
    f[0] = a.x; f[1] = a.y; f[2] = b.x; f[3] = b.y;
}
// helper: unpack 8 e4m3 (u64) to 8 floats
__device__ __forceinline__ void e8_to_f(unsigned long long v, float* f) {
    unsigned short p0 = (unsigned short)v;
    unsigned short p1 = (unsigned short)(v >> 16);
    unsigned short p2 = (unsigned short)(v >> 32);
    unsigned short p3 = (unsigned short)(v >> 48);
    unsigned int h01, h23, h45, h67;
    asm("cvt.rn.f16x2.e4m3x2 %0, %1;" : "=r"(h01) : "h"(p0));
    asm("cvt.rn.f16x2.e4m3x2 %0, %1;" : "=r"(h23) : "h"(p1));
    asm("cvt.rn.f16x2.e4m3x2 %0, %1;" : "=r"(h45) : "h"(p2));
    asm("cvt.rn.f16x2.e4m3x2 %0, %1;" : "=r"(h67) : "h"(p3));
    float2 a = __half22float2(*(__half2*)&h01);
    float2 b = __half22float2(*(__half2*)&h23);
    float2 c = __half22float2(*(__half2*)&h45);
    float2 d = __half22float2(*(__half2*)&h67);
    f[0] = a.x; f[1] = a.y; f[2] = b.x; f[3] = b.y;
    f[4] = c.x; f[5] = c.y; f[6] = d.x; f[7] = d.y;
}

// ---------------------------------------------------------------------------
// fp16 + fp8-residual step (~fp23): grid (64,4), block 512.
// Quarter-warp row parity (4 rows/iter); lane covers 8 cols (uint4 + u64).
__global__ void __launch_bounds__(512) step16r_kernel(int k, int cnt,
                                                      const float* __restrict__ C,
                                                      const float* __restrict__ L) {
    __shared__ __align__(16) float r_s[1024];
    __shared__ float acc_s[16][64];
    __shared__ float dotp_s[2];
    __shared__ float s_sh;

    int tid  = threadIdx.x;
    int lane = tid & 31;
    int w    = tid >> 5;

    PROLOGUE()

    int colbase = blockIdx.x * 64;
    int rowg    = blockIdx.y * 1024 + w * 64;
    int il      = w * 64;
    int quarter = lane >> 3;                         // 0..3: row parity
    int lpos    = lane & 7;                          // col-group (8 cols)
    size_t c16q = (size_t)(colbase >> 3) + lpos;     // uint4 (8 halves), row=512
    size_t cuE  = (size_t)(colbase >> 3) + lpos;     // residual u64, row=512

    const uint4* A16q = (const uint4*)g_Ah;
    const unsigned long long* E8u = g_E8;

    float acc[8];
    #pragma unroll
    for (int c = 0; c < 8; c++) acc[c] = 0.f;

    #pragma unroll 8
    for (int ii = 0; ii < 64; ii += 4) {
        int gr = rowg + ii + quarter;
        float rv = r_s[il + ii + quarter];
        uint4 av = A16q[(size_t)gr * (Nn / 8) + c16q];
        unsigned long long ev = E8u[(size_t)gr * (Nn / 8) + cuE];
        float f[8], e[8];
        h4_to_f(((unsigned long long)av.y << 32) | av.x, f);
        h4_to_f(((unsigned long long)av.w << 32) | av.z, f + 4);
        e8_to_f(ev, e);
        #pragma unroll
        for (int c = 0; c < 8; c++)
            acc[c] += rv * fmaf(e[c], RES_SCALE_INV, f[c]);
    }

    #pragma unroll
    for (int c = 0; c < 8; c++) {
        acc[c] += __shfl_down_sync(0xffffffffu, acc[c], 8);
        acc[c] += __shfl_down_sync(0xffffffffu, acc[c], 16);
    }
    if (lane < 8) {
        #pragma unroll
        for (int c = 0; c < 8; c++)
            acc_s[w][lpos * 8 + c] = acc[c];
    }
    __syncthreads();

    EPILOGUE(t)
}

// ---------------------------------------------------------------------------
// fp16 step: grid (64,4), block 512. Quarter-warp row parity; lane = 8 cols.
__global__ void __launch_bounds__(512) step16_kernel(int k, int cnt,
                                                     const float* __restrict__ C,
                                                     const float* __restrict__ L) {
    __shared__ __align__(16) float r_s[1024];
    __shared__ float acc_s[16][64];
    __shared__ float dotp_s[2];
    __shared__ float s_sh;

    int tid  = threadIdx.x;
    int lane = tid & 31;
    int w    = tid >> 5;

    PROLOGUE()

    int colbase = blockIdx.x * 64;
    int rowg    = blockIdx.y * 1024 + w * 64;
    int il      = w * 64;
    int quarter = lane >> 3;
    int lpos    = lane & 7;
    size_t c16q = (size_t)(colbase >> 3) + lpos;   // uint4 idx, row = 512

    const uint4* A16q = (const uint4*)g_Ah;

    float acc[8];
    #pragma unroll
    for (int c = 0; c < 8; c++) acc[c] = 0.f;

    #pragma unroll 8
    for (int ii = 0; ii < 64; ii += 4) {
        int gr = rowg + ii + quarter;
        float rv = r_s[il + ii + quarter];
        uint4 av = A16q[(size_t)gr * (Nn / 8) + c16q];
        float f[8];
        h4_to_f(((unsigned long long)av.y << 32) | av.x, f);
        h4_to_f(((unsigned long long)av.w << 32) | av.z, f + 4);
        #pragma unroll
        for (int c = 0; c < 8; c++) acc[c] += rv * f[c];
    }

    #pragma unroll
    for (int c = 0; c < 8; c++) {
        acc[c] += __shfl_down_sync(0xffffffffu, acc[c], 8);
        acc[c] += __shfl_down_sync(0xffffffffu, acc[c], 16);
    }
    if (lane < 8) {
        #pragma unroll
        for (int c = 0; c < 8; c++)
            acc_s[w][lpos * 8 + c] = acc[c];
    }
    __syncthreads();

    EPILOGUE(t)
}

// ---------------------------------------------------------------------------
// fp8 step: grid (64,4), block 512. Eighth-warp row parity (8 rows/iter);
// lane covers 16 cols (uint4 = 16 e4m3).
__global__ void __launch_bounds__(512) step8_kernel(int k, int cnt,
                                                    const float* __restrict__ C,
                                                    const float* __restrict__ L) {
    __shared__ __align__(16) float r_s[1024];
    __shared__ float acc_s[16][64];
    __shared__ float dotp_s[2];
    __shared__ float s_sh;

    int tid  = threadIdx.x;
    int lane = tid & 31;
    int w    = tid >> 5;

    PROLOGUE()

    int colbase = blockIdx.x * 64;
    int rowg    = blockIdx.y * 1024 + w * 64;
    int il      = w * 64;
    int eighth  = lane >> 2;                        // 0..7: row parity
    int lpos    = lane & 3;                         // col-group (16 cols)
    size_t cq   = (size_t)(colbase >> 4) + lpos;    // uint4 (16 fp8), row=256

    const uint4* A8q = (const uint4*)g_A8;

    float acc[16];
    #pragma unroll
    for (int c = 0; c < 16; c++) acc[c] = 0.f;

    #pragma unroll 8
    for (int ii = 0; ii < 64; ii += 8) {
        int gr = rowg + ii + eighth;
        float rv = r_s[il + ii + eighth];
        uint4 av = A8q[(size_t)gr * (Nn / 16) + cq];
        float f[16];
        e8_to_f(((unsigned long long)av.y << 32) | av.x, f);
        e8_to_f(((unsigned long long)av.w << 32) | av.z, f + 8);
        #pragma unroll
        for (int c = 0; c < 16; c++) acc[c] += rv * f[c];
    }

    #pragma unroll
    for (int c = 0; c < 16; c++) {
        acc[c] += __shfl_down_sync(0xffffffffu, acc[c], 4);
        acc[c] += __shfl_down_sync(0xffffffffu, acc[c], 8);
        acc[c] += __shfl_down_sync(0xffffffffu, acc[c], 16);
    }
    if (lane < 4) {
        #pragma unroll
        for (int c = 0; c < 16; c++)
            acc_s[w][lpos * 16 + c] = acc[c];
    }
    __syncthreads();

    EPILOGUE(t * FP8_SCALE_INV)
}

// ---------------------------------------------------------------------------
// phi: p_k = r_k B - s_k D, q_k = s_k = r_k.L, a_k = r_k.1
__global__ void __launch_bounds__(256) phi_kernel(const float* __restrict__ B,
                                                  const float* __restrict__ D,
                                                  const float* __restrict__ L) {
    __shared__ float r_s[Nn];
    __shared__ float red[256];
    __shared__ float sres[10];
    int k = blockIdx.x;
    int tid = threadIdx.x;

    for (int i = tid; i < Nn; i += 256)
        r_s[i] = g_R[k][0][i] + g_R[k][1][i] + g_R[k][2][i] + g_R[k][3][i];
    __syncthreads();

    float acc[10];
    #pragma unroll
    for (int c = 0; c < 10; c++) acc[c] = 0.f;

    for (int i = tid; i < Nn; i += 256) {
        float rv = r_s[i];
        float4 b0 = *(const float4*)(B + i * INW);
        float4 b1 = *(const float4*)(B + i * INW + 4);
        acc[0] += rv * b0.x; acc[1] += rv * b0.y;
        acc[2] += rv * b0.z; acc[3] += rv * b0.w;
        acc[4] += rv * b1.x; acc[5] += rv * b1.y;
        acc[6] += rv * b1.z; acc[7] += rv * b1.w;
        acc[8] += rv * L[i];
        acc[9] += rv;                 // h0 = ones
    }

    #pragma unroll
    for (int c = 0; c < 10; c++) {
        red[tid] = acc[c];
        __syncthreads();
        for (int off = 128; off > 0; off >>= 1) {
            if (tid < off) red[tid] += red[tid + off];
            __syncthreads();
        }
        if (tid == 0) sres[c] = red[0];
        __syncthreads();
    }

    if (tid == 0) {
        float s = sres[8];
        #pragma unroll
        for (int c = 0; c < INW; c++) g_PQ[k][c] = sres[c] - s * D[c];
        g_PQ[k][8] = s;
        g_PQ[k][9] = sres[9];
    }
}

// ---------------------------------------------------------------------------
// conv: y_t = a_t + D.u_t + sum_{k<min(t,K)} [ p_k.u_{t-1-k} + q_k yobs_{t-1-k} ]
__global__ void __launch_bounds__(256) conv_kernel(const float* __restrict__ u,
                                                   const float* __restrict__ yobs,
                                                   const float* __restrict__ D,
                                                   float* __restrict__ out) {
    __shared__ float pq[K_TR][10];
    __shared__ float us[512][9];      // [local sidx][0..7]=u, [8]=yobs
    int tid = threadIdx.x;
    int t0  = blockIdx.x * 256;

    for (int idx = tid; idx < K_TR * 10; idx += 256)
        pq[idx / 10][idx % 10] = g_PQ[idx / 10][idx % 10];

    for (int l = tid; l < 512; l += 256) {
        int sidx = t0 - 256 + l;
        if (sidx >= 0 && sidx < Tt) {
            #pragma unroll
            for (int c = 0; c < INW; c++) us[l][c] = u[c * Tt + sidx];
            us[l][8] = yobs[sidx];
        } else {
            #pragma unroll
            for (int c = 0; c < 9; c++) us[l][c] = 0.f;
        }
    }
    __syncthreads();

    int t = t0 + tid;
    float y = 0.f;
    #pragma unroll
    for (int c = 0; c < INW; c++) y += D[c] * u[c * Tt + t];
    if (t < K_TR) y += pq[t][9];      // a_t = r_t . h0 (decayed ~0 beyond K)

    int kmax = min(t, K_TR);
    for (int kk = 0; kk < kmax; kk++) {
        int l = tid + 255 - kk;       // (t-1-kk) - (t0-256)
        float a = pq[kk][8] * us[l][8];
        #pragma unroll
        for (int c = 0; c < INW; c++) a += pq[kk][c] * us[l][c];
        y += a;
    }
    out[t] = 3.f * tanhf(y);
}

// ---------------------------------------------------------------------------
extern "C" void kernel_launch(void* const* d_in, const int* in_sizes, int n_in,
                              void* d_out, int out_size) {
    const float* u    = (const float*)d_in[0];  // [8,4096]
    const float* yobs = (const float*)d_in[1];  // [1,4096]
    const float* A    = (const float*)d_in[2];  // [4096,4096]
    const float* B    = (const float*)d_in[3];  // [4096,8]
    const float* C    = (const float*)d_in[4];  // [1,4096]
    const float* D    = (const float*)d_in[5];  // [1,8]
    const float* L    = (const float*)d_in[6];  // [4096,1]
    float* out = (float*)d_out;                 // [1,4096]
    (void)in_sizes; (void)n_in; (void)out_size;

    convert_kernel<<<(Nn * Nn / 4) / 256, 256>>>((const float4*)A);
    init_kernel<<<Nn / 256, 256>>>(C, L);
    step16r_kernel<<<dim3(64, QP), 512>>>(0, 1, C, L);
    for (int k = 1; k < K_F16R; k++)
        step16r_kernel<<<dim3(64, QP), 512>>>(k, 256, C, L);
    for (int k = K_F16R; k < FP8_START; k++)
        step16_kernel<<<dim3(64, QP), 512>>>(k, 256, C, L);
    for (int k = FP8_START; k < K_TR - 1; k++)
        step8_kernel<<<dim3(64, QP), 512>>>(k, 256, C, L);
    phi_kernel<<<K_TR, 256>>>(B, D, L);
    conv_kernel<<<Tt / 256, 256>>>(u, yobs, D, out);
}